// round 1
// baseline (speedup 1.0000x reference)
#include <cuda_runtime.h>
#include <math.h>

// Problem constants
#define Bq    4
#define Hq    256
#define Wq    256
#define Tt    3
#define Dd    64
#define NPIX  (Bq * Hq * Wq)          // 262144
#define PPB   32                       // pixels per block
#define THREADS 256
#define NBLOCKS (NPIX / PPB)           // 8192

// Shared memory layout (floats)
//   xs  : [192][32]   = 6144
//   w1s : [128][64]   = 8192   (reused as out staging [64][32] in epilogue)
//   wfs : [192][64]   = 12288
//   b1s : 64, w2s : 64, bfs : 64, ss : [6][32] = 192
#define SM_FLOATS (6144 + 8192 + 12288 + 64 + 64 + 64 + 192)
#define SM_BYTES  (SM_FLOATS * 4)

__device__ __forceinline__ float gelu_exact(float x) {
    // jax.nn.gelu(approximate=False) = x * Phi(x)
    return x * normcdff(x);
}

__global__ void __launch_bounds__(THREADS, 2)
dig_kernel(const float* __restrict__ deg,
           const float* __restrict__ W1,
           const float* __restrict__ b1,
           const float* __restrict__ W2,
           const float* __restrict__ b2,
           const float* __restrict__ Wf,
           const float* __restrict__ bf,
           float* __restrict__ out)
{
    extern __shared__ float sm[];
    float* xs  = sm;                 // [192][32]
    float* w1s = xs  + 6144;         // [128][64]
    float* wfs = w1s + 8192;         // [192][64]
    float* b1s = wfs + 12288;        // [64]
    float* w2s = b1s + 64;           // [64]
    float* bfs = w2s + 64;           // [64]
    float* ss  = bfs + 64;           // [6][32]

    const int tid = threadIdx.x;
    const int pix = tid >> 3;        // 0..31
    const int sub = tid & 7;         // 0..7

    const int base = blockIdx.x * PPB;     // linear pixel base
    const int b    = base >> 16;           // / (H*W)
    const int hw   = base & 65535;         // within image plane

    // ---------------- Phase 1: cooperative loads ----------------
    {
        const float* dbase = deg + (size_t)b * 192 * 65536 + hw;
        #pragma unroll
        for (int i = tid; i < 192 * PPB; i += THREADS) {
            int ch = i >> 5, p = i & 31;
            xs[i] = dbase[(size_t)ch * 65536 + p];
        }
        for (int i = tid; i < 8192; i += THREADS)  w1s[i] = W1[i];
        for (int i = tid; i < 12288; i += THREADS) wfs[i] = Wf[i];
        if (tid < 64) {
            b1s[tid] = b1[tid];
            w2s[tid] = W2[tid];
            bfs[tid] = bf[tid];
        }
    }
    __syncthreads();

    // ---------------- Phase 2: pair gate scores s_ij ----------------
    // thread (pix, sub) owns e = sub*8 .. sub*8+7 ; accumulates a[t][k], c[t][k]
    {
        const int e0 = sub * 8;
        float a0[8], a1[8], a2[8], c0[8], c1[8], c2[8];
        #pragma unroll
        for (int k = 0; k < 8; k++) { a0[k]=a1[k]=a2[k]=c0[k]=c1[k]=c2[k]=0.f; }

        const float* xp = xs + pix;
        #pragma unroll 2
        for (int d = 0; d < 64; d++) {
            float x0 = xp[d * 32];
            float x1 = xp[(64 + d) * 32];
            float x2 = xp[(128 + d) * 32];
            const float4 wa0 = *reinterpret_cast<const float4*>(w1s + d * 64 + e0);
            const float4 wa1 = *reinterpret_cast<const float4*>(w1s + d * 64 + e0 + 4);
            const float4 wc0 = *reinterpret_cast<const float4*>(w1s + (64 + d) * 64 + e0);
            const float4 wc1 = *reinterpret_cast<const float4*>(w1s + (64 + d) * 64 + e0 + 4);
            float wa[8] = {wa0.x, wa0.y, wa0.z, wa0.w, wa1.x, wa1.y, wa1.z, wa1.w};
            float wc[8] = {wc0.x, wc0.y, wc0.z, wc0.w, wc1.x, wc1.y, wc1.z, wc1.w};
            #pragma unroll
            for (int k = 0; k < 8; k++) {
                a0[k] = fmaf(x0, wa[k], a0[k]);
                a1[k] = fmaf(x1, wa[k], a1[k]);
                a2[k] = fmaf(x2, wa[k], a2[k]);
                c0[k] = fmaf(x0, wc[k], c0[k]);
                c1[k] = fmaf(x1, wc[k], c1[k]);
                c2[k] = fmaf(x2, wc[k], c2[k]);
            }
        }

        // pair partial sums over this thread's 8 e-values
        // pair order: 0:(0,1) 1:(0,2) 2:(1,0) 3:(1,2) 4:(2,0) 5:(2,1)
        float sp[6] = {0.f, 0.f, 0.f, 0.f, 0.f, 0.f};
        #pragma unroll
        for (int k = 0; k < 8; k++) {
            const float bb  = b1s[e0 + k];
            const float w2v = w2s[e0 + k];
            sp[0] = fmaf(gelu_exact(a0[k] + c1[k] + bb), w2v, sp[0]);
            sp[1] = fmaf(gelu_exact(a0[k] + c2[k] + bb), w2v, sp[1]);
            sp[2] = fmaf(gelu_exact(a1[k] + c0[k] + bb), w2v, sp[2]);
            sp[3] = fmaf(gelu_exact(a1[k] + c2[k] + bb), w2v, sp[3]);
            sp[4] = fmaf(gelu_exact(a2[k] + c0[k] + bb), w2v, sp[4]);
            sp[5] = fmaf(gelu_exact(a2[k] + c1[k] + bb), w2v, sp[5]);
        }
        // reduce across the 8 threads of this pixel (contiguous lanes)
        #pragma unroll
        for (int q = 0; q < 6; q++) {
            #pragma unroll
            for (int off = 4; off > 0; off >>= 1)
                sp[q] += __shfl_down_sync(0xffffffffu, sp[q], off, 8);
        }
        if (sub == 0) {
            const float b2v = b2[0];
            #pragma unroll
            for (int q = 0; q < 6; q++) {
                float v = sp[q] + b2v;
                ss[q * 32 + pix] = 1.0f / (1.0f + expf(-v));
            }
        }
    }
    __syncthreads();

    // ---------------- Phase 3: mix + final projection (Wf) ----------------
    {
        // M[i][j]: M[i][i]=1, M[i][j]=s_ij
        float m[3][3];
        m[0][0] = 1.f; m[0][1] = ss[0 * 32 + pix]; m[0][2] = ss[1 * 32 + pix];
        m[1][0] = ss[2 * 32 + pix]; m[1][1] = 1.f; m[1][2] = ss[3 * 32 + pix];
        m[2][0] = ss[4 * 32 + pix]; m[2][1] = ss[5 * 32 + pix]; m[2][2] = 1.f;

        const int o0 = sub * 8;
        float acc[8];
        #pragma unroll
        for (int k = 0; k < 8; k++) acc[k] = bfs[o0 + k];

        const float* xp = xs + pix;
        #pragma unroll
        for (int t = 0; t < 3; t++) {
            const float mt0 = m[t][0], mt1 = m[t][1], mt2 = m[t][2];
            #pragma unroll 4
            for (int d = 0; d < 64; d++) {
                float y = fmaf(mt0, xp[d * 32],
                          fmaf(mt1, xp[(64 + d) * 32],
                               mt2 * xp[(128 + d) * 32]));
                const float4 wf0 = *reinterpret_cast<const float4*>(wfs + (t * 64 + d) * 64 + o0);
                const float4 wf1 = *reinterpret_cast<const float4*>(wfs + (t * 64 + d) * 64 + o0 + 4);
                acc[0] = fmaf(y, wf0.x, acc[0]);
                acc[1] = fmaf(y, wf0.y, acc[1]);
                acc[2] = fmaf(y, wf0.z, acc[2]);
                acc[3] = fmaf(y, wf0.w, acc[3]);
                acc[4] = fmaf(y, wf1.x, acc[4]);
                acc[5] = fmaf(y, wf1.y, acc[5]);
                acc[6] = fmaf(y, wf1.z, acc[6]);
                acc[7] = fmaf(y, wf1.w, acc[7]);
            }
        }

        // stage into shared (reuse w1s region) for coalesced global stores
        float* outs = w1s;  // [64][32]
        #pragma unroll
        for (int k = 0; k < 8; k++) outs[(o0 + k) * 32 + pix] = acc[k];
    }
    __syncthreads();

    // coalesced write-back: out[b, o, h, w]
    {
        float* obase = out + (size_t)b * 64 * 65536 + hw;
        const float* outs = w1s;
        #pragma unroll
        for (int i = tid; i < 64 * PPB; i += THREADS) {
            int o = i >> 5, p = i & 31;
            obase[(size_t)o * 65536 + p] = outs[i];
        }
    }
}

extern "C" void kernel_launch(void* const* d_in, const int* in_sizes, int n_in,
                              void* d_out, int out_size)
{
    const float* deg = (const float*)d_in[0];
    const float* W1  = (const float*)d_in[1];
    const float* b1  = (const float*)d_in[2];
    const float* W2  = (const float*)d_in[3];
    const float* b2  = (const float*)d_in[4];
    const float* Wf  = (const float*)d_in[5];
    const float* bf  = (const float*)d_in[6];
    float* out = (float*)d_out;

    cudaFuncSetAttribute(dig_kernel, cudaFuncAttributeMaxDynamicSharedMemorySize, SM_BYTES);
    dig_kernel<<<NBLOCKS, THREADS, SM_BYTES>>>(deg, W1, b1, W2, b2, Wf, bf, out);
}

// round 3
// speedup vs baseline: 2.8818x; 2.8818x over previous
#include <cuda_runtime.h>
#include <cstdint>
#include <math.h>

#define THREADS  256
#define PPB      128
#define NBLOCKS  2048

// ---- smem layout (floats / u32 words) ----
// xs  : [192][132] fp32 X (later Y in place)            = 101376 B
// b1w : [128][68]  tf32 bits of [W1a^T ; W1c^T]         =  34816 B  (reused as stg[64][132])
// b2w : [64][196]  tf32 bits of Wf^T                    =  50176 B
// smalls: b1s[64] w2s[64] bfs[64] ss[6*128]
#define XS_W   132
#define B1_W   68
#define B2_W   196
#define XS_OFF 0
#define B1_OFF (192 * XS_W)                 // 25344 floats
#define B2_OFF (B1_OFF + 128 * B1_W)        // 34048
#define SM_B1S (B2_OFF + 64 * B2_W)         // 46592
#define SM_W2S (SM_B1S + 64)
#define SM_BFS (SM_W2S + 64)
#define SM_SS  (SM_BFS + 64)
#define SM_FLOATS (SM_SS + 6 * 128)
#define SM_BYTES (SM_FLOATS * 4)            // ~190.6 KB

__device__ __forceinline__ uint32_t f2tf32(float v) {
    uint32_t o;
    asm("cvt.rna.tf32.f32 %0, %1;" : "=r"(o) : "f"(v));
    return o;
}
__device__ __forceinline__ void mma8(float d[4], const uint32_t a[4],
                                     uint32_t b0, uint32_t b1) {
    asm volatile(
        "mma.sync.aligned.m16n8k8.row.col.f32.tf32.tf32.f32 "
        "{%0,%1,%2,%3}, {%4,%5,%6,%7}, {%8,%9}, {%0,%1,%2,%3};"
        : "+f"(d[0]), "+f"(d[1]), "+f"(d[2]), "+f"(d[3])
        : "r"(a[0]), "r"(a[1]), "r"(a[2]), "r"(a[3]), "r"(b0), "r"(b1));
}
__device__ __forceinline__ float gelu_exact(float h) {
    return 0.5f * h * (1.0f + erff(h * 0.70710678118654752f));
}

__global__ void __launch_bounds__(THREADS, 1)
dig_mma(const float* __restrict__ deg,
        const float* __restrict__ W1,
        const float* __restrict__ b1,
        const float* __restrict__ W2,
        const float* __restrict__ b2,
        const float* __restrict__ Wf,
        const float* __restrict__ bf,
        float* __restrict__ out)
{
    extern __shared__ float sm[];
    float*    xs  = sm + XS_OFF;
    uint32_t* b1w = (uint32_t*)(sm + B1_OFF);
    uint32_t* b2w = (uint32_t*)(sm + B2_OFF);
    float*    b1s = sm + SM_B1S;
    float*    w2s = sm + SM_W2S;
    float*    bfs = sm + SM_BFS;
    float*    ss  = sm + SM_SS;      // [6][128]

    const int tid  = threadIdx.x;
    const int wid  = tid >> 5;
    const int lane = tid & 31;
    const int g    = lane >> 2;      // groupID 0..7
    const int tig  = lane & 3;       // thread-in-group 0..3
    const int m0   = wid << 4;       // 16 pixels per warp

    const int bb  = blockIdx.x >> 9;
    const int hw0 = (blockIdx.x & 511) << 7;

    // ---------------- stage ----------------
    {
        const float* dptr = deg + (size_t)bb * 192 * 65536 + hw0;
        #pragma unroll 4
        for (int i = tid; i < 192 * 128; i += THREADS) {
            int c = i >> 7, p = i & 127;
            xs[c * XS_W + p] = dptr[(size_t)c * 65536 + p];
        }
    }
    #pragma unroll 4
    for (int i = tid; i < 8192; i += THREADS) {          // W1 [128 d'][64 e]
        int r = i >> 6, e = i & 63;
        int n = (r < 64) ? e : (64 + e);
        int k = r & 63;
        b1w[n * B1_W + k] = f2tf32(W1[i]);
    }
    #pragma unroll 4
    for (int i = tid; i < 12288; i += THREADS) {         // Wf [192][64]
        int r = i >> 6, c = i & 63;
        b2w[c * B2_W + r] = f2tf32(Wf[i]);
    }
    if (tid < 64) { b1s[tid] = b1[tid]; w2s[tid] = W2[tid]; bfs[tid] = bf[tid]; }
    __syncthreads();

    // -------- GEMM1 (tf32 MMA) + in-register gating --------
    float sp[6][2] = {{0.f,0.f},{0.f,0.f},{0.f,0.f},{0.f,0.f},{0.f,0.f},{0.f,0.f}};
    #pragma unroll
    for (int half = 0; half < 2; half++) {
        float accA[3][4][4], accC[3][4][4];
        #pragma unroll
        for (int t = 0; t < 3; t++)
            #pragma unroll
            for (int n = 0; n < 4; n++)
                #pragma unroll
                for (int r = 0; r < 4; r++) { accA[t][n][r] = 0.f; accC[t][n][r] = 0.f; }

        #pragma unroll
        for (int k = 0; k < 8; k++) {
            uint32_t af[3][4];
            #pragma unroll
            for (int t = 0; t < 3; t++) {
                const int c0 = t * 64 + k * 8;
                af[t][0] = f2tf32(xs[(c0 + tig)     * XS_W + m0 + g]);
                af[t][1] = f2tf32(xs[(c0 + tig)     * XS_W + m0 + g + 8]);
                af[t][2] = f2tf32(xs[(c0 + tig + 4) * XS_W + m0 + g]);
                af[t][3] = f2tf32(xs[(c0 + tig + 4) * XS_W + m0 + g + 8]);
            }
            #pragma unroll
            for (int na = 0; na < 4; na++) {
                const int n = half * 32 + na * 8 + g;
                uint32_t bb0 = b1w[n * B1_W + k * 8 + tig];
                uint32_t bb1 = b1w[n * B1_W + k * 8 + tig + 4];
                #pragma unroll
                for (int t = 0; t < 3; t++) mma8(accA[t][na], af[t], bb0, bb1);
            }
            #pragma unroll
            for (int nc = 0; nc < 4; nc++) {
                const int n = 64 + half * 32 + nc * 8 + g;
                uint32_t bb0 = b1w[n * B1_W + k * 8 + tig];
                uint32_t bb1 = b1w[n * B1_W + k * 8 + tig + 4];
                #pragma unroll
                for (int t = 0; t < 3; t++) mma8(accC[t][nc], af[t], bb0, bb1);
            }
        }
        // gating partials: accum reg (r,cc) -> row m0+g+8r, e = half*32+na*8+2*tig+cc
        #pragma unroll
        for (int na = 0; na < 4; na++) {
            #pragma unroll
            for (int cc = 0; cc < 2; cc++) {
                const int e = half * 32 + na * 8 + 2 * tig + cc;
                const float bbv = b1s[e];
                const float wv  = w2s[e];
                #pragma unroll
                for (int r = 0; r < 2; r++) {
                    const int ri = 2 * r + cc;
                    // pairs: 0:(0,1) 1:(0,2) 2:(1,0) 3:(1,2) 4:(2,0) 5:(2,1)
                    sp[0][r] = fmaf(gelu_exact(accA[0][na][ri] + accC[1][na][ri] + bbv), wv, sp[0][r]);
                    sp[1][r] = fmaf(gelu_exact(accA[0][na][ri] + accC[2][na][ri] + bbv), wv, sp[1][r]);
                    sp[2][r] = fmaf(gelu_exact(accA[1][na][ri] + accC[0][na][ri] + bbv), wv, sp[2][r]);
                    sp[3][r] = fmaf(gelu_exact(accA[1][na][ri] + accC[2][na][ri] + bbv), wv, sp[3][r]);
                    sp[4][r] = fmaf(gelu_exact(accA[2][na][ri] + accC[0][na][ri] + bbv), wv, sp[4][r]);
                    sp[5][r] = fmaf(gelu_exact(accA[2][na][ri] + accC[1][na][ri] + bbv), wv, sp[5][r]);
                }
            }
        }
    }
    // reduce over the 4 lanes of each group (consecutive lanes), sigmoid, store s
    {
        const float b2v = b2[0];
        #pragma unroll
        for (int q = 0; q < 6; q++) {
            #pragma unroll
            for (int r = 0; r < 2; r++) {
                float v = sp[q][r];
                v += __shfl_down_sync(0xffffffffu, v, 2, 4);
                v += __shfl_down_sync(0xffffffffu, v, 1, 4);
                if (tig == 0)
                    ss[q * 128 + m0 + g + 8 * r] = 1.0f / (1.0f + __expf(-(v + b2v)));
            }
        }
    }
    __syncthreads();

    // -------- Y phase: xs <- M * x in place (fp32, exclusive per thread) --------
    {
        const int p  = tid & 127;
        const int d0 = (tid >> 7) * 32;
        const float m01 = ss[0 * 128 + p], m02 = ss[1 * 128 + p];
        const float m10 = ss[2 * 128 + p], m12 = ss[3 * 128 + p];
        const float m20 = ss[4 * 128 + p], m21 = ss[5 * 128 + p];
        #pragma unroll 4
        for (int d = d0; d < d0 + 32; d++) {
            float x0 = xs[d * XS_W + p];
            float x1 = xs[(64 + d) * XS_W + p];
            float x2 = xs[(128 + d) * XS_W + p];
            xs[d * XS_W + p]         = fmaf(m02, x2, fmaf(m01, x1, x0));
            xs[(64 + d) * XS_W + p]  = fmaf(m12, x2, fmaf(m10, x0, x1));
            xs[(128 + d) * XS_W + p] = fmaf(m21, x1, fmaf(m20, x0, x2));
        }
    }
    __syncthreads();

    // -------- GEMM2: D[128,64] = Y[128,192] @ Wf (tf32 MMA) --------
    float D[8][4];
    #pragma unroll
    for (int n = 0; n < 8; n++)
        #pragma unroll
        for (int r = 0; r < 4; r++) D[n][r] = 0.f;

    #pragma unroll 4
    for (int k = 0; k < 24; k++) {
        const int c0 = k * 8;
        uint32_t af[4];
        af[0] = f2tf32(xs[(c0 + tig)     * XS_W + m0 + g]);
        af[1] = f2tf32(xs[(c0 + tig)     * XS_W + m0 + g + 8]);
        af[2] = f2tf32(xs[(c0 + tig + 4) * XS_W + m0 + g]);
        af[3] = f2tf32(xs[(c0 + tig + 4) * XS_W + m0 + g + 8]);
        #pragma unroll
        for (int n = 0; n < 8; n++) {
            uint32_t bb0 = b2w[(n * 8 + g) * B2_W + c0 + tig];
            uint32_t bb1 = b2w[(n * 8 + g) * B2_W + c0 + tig + 4];
            mma8(D[n], af, bb0, bb1);
        }
    }
    __syncthreads();   // b1w region free now -> reuse as staging

    // -------- epilogue: + bf, stage, coalesced store --------
    {
        float* stg = (float*)b1w;    // [64][132]
        #pragma unroll
        for (int n = 0; n < 8; n++) {
            #pragma unroll
            for (int cc = 0; cc < 2; cc++) {
                const int col = n * 8 + 2 * tig + cc;
                const float bfv = bfs[col];
                stg[col * XS_W + m0 + g]     = D[n][cc]     + bfv;
                stg[col * XS_W + m0 + g + 8] = D[n][2 + cc] + bfv;
            }
        }
    }
    __syncthreads();
    {
        float* op = out + (size_t)bb * 64 * 65536 + hw0;
        const float* stg = (const float*)b1w;
        #pragma unroll 4
        for (int i = tid; i < 64 * 128; i += THREADS) {
            int o = i >> 7, p = i & 127;
            op[(size_t)o * 65536 + p] = stg[o * XS_W + p];
        }
    }
}

extern "C" void kernel_launch(void* const* d_in, const int* in_sizes, int n_in,
                              void* d_out, int out_size)
{
    const float* deg = (const float*)d_in[0];
    const float* W1  = (const float*)d_in[1];
    const float* b1  = (const float*)d_in[2];
    const float* W2  = (const float*)d_in[3];
    const float* b2  = (const float*)d_in[4];
    const float* Wf  = (const float*)d_in[5];
    const float* bf  = (const float*)d_in[6];
    float* outp = (float*)d_out;

    cudaFuncSetAttribute(dig_mma, cudaFuncAttributeMaxDynamicSharedMemorySize, SM_BYTES);
    dig_mma<<<NBLOCKS, THREADS, SM_BYTES>>>(deg, W1, b1, W2, b2, Wf, bf, outp);
}

// round 4
// speedup vs baseline: 4.0706x; 1.4125x over previous
#include <cuda_runtime.h>
#include <cstdint>
#include <math.h>

#define THREADS  512
#define PPB      128
#define NBLOCKS  2048

// ---- smem layout (32-bit words) ----
// xs  : [192][136]  tf32 bits of X (later Y bits in place); epilogue: stgA[64][136]
// b1w : [128][68]   tf32 bits of [W1a^T ; W1c^T]; epilogue: stgB[64][132]
// b2w : [64][196]   tf32 bits of Wf^T
// smalls: b1s[64] w2s[64] bfs[64] sspart[2][6][128] ss[6][128]
#define XS_W   136
#define B1_W   68
#define B2_W   196
#define XS_OFF 0
#define B1_OFF (192 * XS_W)                 // 26112
#define B2_OFF (B1_OFF + 128 * B1_W)        // 34816
#define SM_B1S (B2_OFF + 64 * B2_W)         // 47360
#define SM_W2S (SM_B1S + 64)
#define SM_BFS (SM_W2S + 64)
#define SM_SSP (SM_BFS + 64)                // 2*6*128 = 1536
#define SM_SS  (SM_SSP + 1536)              // 6*128 = 768
#define SM_FLOATS (SM_SS + 768)
#define SM_BYTES (SM_FLOATS * 4)            // 199424 B

__device__ __forceinline__ uint32_t f2tf32(float v) {
    uint32_t o;
    asm("cvt.rna.tf32.f32 %0, %1;" : "=r"(o) : "f"(v));
    return o;
}
__device__ __forceinline__ void mma8(float d[4], const uint32_t a[4],
                                     uint32_t b0, uint32_t b1) {
    asm volatile(
        "mma.sync.aligned.m16n8k8.row.col.f32.tf32.tf32.f32 "
        "{%0,%1,%2,%3}, {%4,%5,%6,%7}, {%8,%9}, {%0,%1,%2,%3};"
        : "+f"(d[0]), "+f"(d[1]), "+f"(d[2]), "+f"(d[3])
        : "r"(a[0]), "r"(a[1]), "r"(a[2]), "r"(a[3]), "r"(b0), "r"(b1));
}
__device__ __forceinline__ float gelu_exact(float h) {
    return 0.5f * h * (1.0f + erff(h * 0.70710678118654752f));
}

__global__ void __launch_bounds__(THREADS, 1)
dig_mma2(const float* __restrict__ deg,
         const float* __restrict__ W1,
         const float* __restrict__ b1,
         const float* __restrict__ W2,
         const float* __restrict__ b2,
         const float* __restrict__ Wf,
         const float* __restrict__ bf,
         float* __restrict__ out)
{
    extern __shared__ float sm[];
    uint32_t* xw  = (uint32_t*)(sm + XS_OFF);   // tf32 bits
    float*    xs  = sm + XS_OFF;                // same memory viewed as float
    uint32_t* b1w = (uint32_t*)(sm + B1_OFF);
    uint32_t* b2w = (uint32_t*)(sm + B2_OFF);
    float*    b1s = sm + SM_B1S;
    float*    w2s = sm + SM_W2S;
    float*    bfs = sm + SM_BFS;
    float*    ssp = sm + SM_SSP;     // [2][6][128]
    float*    ss  = sm + SM_SS;      // [6][128]

    const int tid  = threadIdx.x;
    const int wid  = tid >> 5;
    const int lane = tid & 31;
    const int g    = lane >> 2;      // 0..7
    const int tig  = lane & 3;       // 0..3
    const int m0   = (wid & 7) << 4; // 16-pixel tile per warp
    const int half = wid >> 3;       // 0/1 : e-half (GEMM1) / k-half (GEMM2)

    const int bb  = blockIdx.x >> 9;
    const int hw0 = (blockIdx.x & 511) << 7;

    // ---------------- stage (pre-converted to tf32 bits) ----------------
    {
        const float* dptr = deg + (size_t)bb * 192 * 65536 + hw0;
        #pragma unroll 4
        for (int i = tid; i < 192 * 128; i += THREADS) {
            int c = i >> 7, p = i & 127;
            xw[c * XS_W + p] = f2tf32(dptr[(size_t)c * 65536 + p]);
        }
    }
    #pragma unroll 4
    for (int i = tid; i < 8192; i += THREADS) {          // W1 [128 d'][64 e]
        int r = i >> 6, e = i & 63;
        int n = (r < 64) ? e : (64 + e);
        int k = r & 63;
        b1w[n * B1_W + k] = f2tf32(W1[i]);
    }
    #pragma unroll 4
    for (int i = tid; i < 12288; i += THREADS) {         // Wf [192][64]
        int r = i >> 6, c = i & 63;
        b2w[c * B2_W + r] = f2tf32(Wf[i]);
    }
    if (tid < 64) { b1s[tid] = b1[tid]; w2s[tid] = W2[tid]; bfs[tid] = bf[tid]; }
    __syncthreads();

    // -------- GEMM1 (tf32 MMA) + in-register gating, e-half per warp --------
    float sp[6][2] = {{0.f,0.f},{0.f,0.f},{0.f,0.f},{0.f,0.f},{0.f,0.f},{0.f,0.f}};
    const uint32_t* xpt = xw + tig * XS_W + m0 + g;   // A fragment base
    #pragma unroll
    for (int qq = 0; qq < 2; qq++) {
        const int qt = half * 2 + qq;                 // e-quarter 0..3
        float accA[3][2][4], accC[3][2][4];
        #pragma unroll
        for (int t = 0; t < 3; t++)
            #pragma unroll
            for (int n = 0; n < 2; n++)
                #pragma unroll
                for (int r = 0; r < 4; r++) { accA[t][n][r] = 0.f; accC[t][n][r] = 0.f; }

        #pragma unroll
        for (int k = 0; k < 8; k++) {
            uint32_t af[3][4];
            #pragma unroll
            for (int t = 0; t < 3; t++) {
                const int c0 = t * 64 + k * 8;
                af[t][0] = xpt[c0 * XS_W];
                af[t][1] = xpt[c0 * XS_W + 8];
                af[t][2] = xpt[(c0 + 4) * XS_W];
                af[t][3] = xpt[(c0 + 4) * XS_W + 8];
            }
            #pragma unroll
            for (int nt = 0; nt < 2; nt++) {
                const int nA = qt * 16 + nt * 8 + g;
                uint32_t a0 = b1w[nA * B1_W + k * 8 + tig];
                uint32_t a1 = b1w[nA * B1_W + k * 8 + tig + 4];
                #pragma unroll
                for (int t = 0; t < 3; t++) mma8(accA[t][nt], af[t], a0, a1);
                const int nC = 64 + qt * 16 + nt * 8 + g;
                uint32_t c0b = b1w[nC * B1_W + k * 8 + tig];
                uint32_t c1b = b1w[nC * B1_W + k * 8 + tig + 4];
                #pragma unroll
                for (int t = 0; t < 3; t++) mma8(accC[t][nt], af[t], c0b, c1b);
            }
        }
        // gating partials: accum reg (r,cc) -> pixel row m0+g+8r, e = qt*16+nt*8+2*tig+cc
        #pragma unroll
        for (int nt = 0; nt < 2; nt++) {
            #pragma unroll
            for (int cc = 0; cc < 2; cc++) {
                const int e = qt * 16 + nt * 8 + 2 * tig + cc;
                const float bbv = b1s[e];
                const float wv  = w2s[e];
                #pragma unroll
                for (int r = 0; r < 2; r++) {
                    const int ri = 2 * r + cc;
                    // pairs: 0:(0,1) 1:(0,2) 2:(1,0) 3:(1,2) 4:(2,0) 5:(2,1)
                    sp[0][r] = fmaf(gelu_exact(accA[0][nt][ri] + accC[1][nt][ri] + bbv), wv, sp[0][r]);
                    sp[1][r] = fmaf(gelu_exact(accA[0][nt][ri] + accC[2][nt][ri] + bbv), wv, sp[1][r]);
                    sp[2][r] = fmaf(gelu_exact(accA[1][nt][ri] + accC[0][nt][ri] + bbv), wv, sp[2][r]);
                    sp[3][r] = fmaf(gelu_exact(accA[1][nt][ri] + accC[2][nt][ri] + bbv), wv, sp[3][r]);
                    sp[4][r] = fmaf(gelu_exact(accA[2][nt][ri] + accC[0][nt][ri] + bbv), wv, sp[4][r]);
                    sp[5][r] = fmaf(gelu_exact(accA[2][nt][ri] + accC[1][nt][ri] + bbv), wv, sp[5][r]);
                }
            }
        }
    }
    // 4-lane reduce within group, write per-half partials
    {
        #pragma unroll
        for (int q = 0; q < 6; q++) {
            #pragma unroll
            for (int r = 0; r < 2; r++) {
                float v = sp[q][r];
                v += __shfl_down_sync(0xffffffffu, v, 2, 4);
                v += __shfl_down_sync(0xffffffffu, v, 1, 4);
                if (tig == 0)
                    ssp[half * 768 + q * 128 + m0 + g + 8 * r] = v;
            }
        }
    }
    __syncthreads();
    // combine halves + sigmoid
    {
        const float b2v = b2[0];
        #pragma unroll
        for (int i = tid; i < 768; i += THREADS)
            ss[i] = 1.0f / (1.0f + __expf(-(ssp[i] + ssp[768 + i] + b2v)));
    }
    __syncthreads();

    // -------- Y phase: xs <- M * x in place (exclusive per thread) --------
    {
        const int p  = tid & 127;
        const int d0 = (tid >> 7) << 4;   // 16 d per thread
        const float m01 = ss[0 * 128 + p], m02 = ss[1 * 128 + p];
        const float m10 = ss[2 * 128 + p], m12 = ss[3 * 128 + p];
        const float m20 = ss[4 * 128 + p], m21 = ss[5 * 128 + p];
        #pragma unroll 4
        for (int d = d0; d < d0 + 16; d++) {
            float x0 = xs[d * XS_W + p];
            float x1 = xs[(64 + d) * XS_W + p];
            float x2 = xs[(128 + d) * XS_W + p];
            xw[d * XS_W + p]         = f2tf32(fmaf(m02, x2, fmaf(m01, x1, x0)));
            xw[(64 + d) * XS_W + p]  = f2tf32(fmaf(m12, x2, fmaf(m10, x0, x1)));
            xw[(128 + d) * XS_W + p] = f2tf32(fmaf(m21, x1, fmaf(m20, x0, x2)));
        }
    }
    __syncthreads();

    // -------- GEMM2: D[128,64] = Y[128,192] @ Wf, k-half per warp --------
    float D[8][4];
    #pragma unroll
    for (int n = 0; n < 8; n++)
        #pragma unroll
        for (int r = 0; r < 4; r++) D[n][r] = 0.f;

    {
        const int k0 = half * 12;
        #pragma unroll 4
        for (int k = k0; k < k0 + 12; k++) {
            const int c0 = k * 8;
            uint32_t af[4];
            af[0] = xpt[c0 * XS_W];
            af[1] = xpt[c0 * XS_W + 8];
            af[2] = xpt[(c0 + 4) * XS_W];
            af[3] = xpt[(c0 + 4) * XS_W + 8];
            #pragma unroll
            for (int n = 0; n < 8; n++) {
                uint32_t bb0 = b2w[(n * 8 + g) * B2_W + c0 + tig];
                uint32_t bb1 = b2w[(n * 8 + g) * B2_W + c0 + tig + 4];
                mma8(D[n], af, bb0, bb1);
            }
        }
    }
    __syncthreads();   // all reads of xs / b2w complete

    // -------- cross-half D reduction + epilogue --------
    float* stgB = (float*)b1w;       // [64][132] raw half-1 partials
    if (half == 1) {
        #pragma unroll
        for (int n = 0; n < 8; n++) {
            #pragma unroll
            for (int cc = 0; cc < 2; cc++) {
                const int col = n * 8 + 2 * tig + cc;
                stgB[col * 132 + m0 + g]     = D[n][cc];
                stgB[col * 132 + m0 + g + 8] = D[n][2 + cc];
            }
        }
    }
    __syncthreads();
    float* stgA = sm + XS_OFF;       // reuse xs region: [64][136] final
    if (half == 0) {
        #pragma unroll
        for (int n = 0; n < 8; n++) {
            #pragma unroll
            for (int cc = 0; cc < 2; cc++) {
                const int col = n * 8 + 2 * tig + cc;
                const float bfv = bfs[col];
                stgA[col * XS_W + m0 + g] =
                    D[n][cc] + stgB[col * 132 + m0 + g] + bfv;
                stgA[col * XS_W + m0 + g + 8] =
                    D[n][2 + cc] + stgB[col * 132 + m0 + g + 8] + bfv;
            }
        }
    }
    __syncthreads();
    {
        float* op = out + (size_t)bb * 64 * 65536 + hw0;
        #pragma unroll 4
        for (int i = tid; i < 64 * 128; i += THREADS) {
            int o = i >> 7, p = i & 127;
            op[(size_t)o * 65536 + p] = stgA[o * XS_W + p];
        }
    }
}

extern "C" void kernel_launch(void* const* d_in, const int* in_sizes, int n_in,
                              void* d_out, int out_size)
{
    const float* deg = (const float*)d_in[0];
    const float* W1  = (const float*)d_in[1];
    const float* b1  = (const float*)d_in[2];
    const float* W2  = (const float*)d_in[3];
    const float* b2  = (const float*)d_in[4];
    const float* Wf  = (const float*)d_in[5];
    const float* bf  = (const float*)d_in[6];
    float* outp = (float*)d_out;

    cudaFuncSetAttribute(dig_mma2, cudaFuncAttributeMaxDynamicSharedMemorySize, SM_BYTES);
    dig_mma2<<<NBLOCKS, THREADS, SM_BYTES>>>(deg, W1, b1, W2, b2, Wf, bf, outp);
}

// round 5
// speedup vs baseline: 4.6957x; 1.1535x over previous
#include <cuda_runtime.h>
#include <cstdint>
#include <math.h>

#define THREADS  512
#define PPB      128
#define NBLOCKS  2048

// ---- smem layout (32-bit words) ----
// xs  : [192][136] tf32 bits of X (later Y bits); epilogue reuse: stgA[64][136]
// b1f : 8192 words, fragment-major [kb(8)][nb(16)][lane(32)][2]  (W1a^T;W1c^T)
// b2f : 12288 words, fragment-major [kb(24)][nb(8)][lane(32)][2] (Wf^T)
//       b1f+b2f region reused as stgB[64][132] in epilogue
#define XS_W   136
#define XS_OFF 0
#define B1_OFF (192 * XS_W)                 // 26112
#define B2_OFF (B1_OFF + 8192)              // 34304
#define SM_B1S (B2_OFF + 12288)             // 46592
#define SM_W2S (SM_B1S + 64)
#define SM_BFS (SM_W2S + 64)
#define SM_SSP (SM_BFS + 64)                // 2*6*128
#define SM_SS  (SM_SSP + 1536)              // 6*128
#define SM_FLOATS (SM_SS + 768)
#define SM_BYTES (SM_FLOATS * 4)

__device__ __forceinline__ uint32_t f2tf32(float v) {
    uint32_t o;
    asm("cvt.rna.tf32.f32 %0, %1;" : "=r"(o) : "f"(v));
    return o;
}
__device__ __forceinline__ void mma8(float d[4], const uint32_t a[4],
                                     uint32_t b0, uint32_t b1) {
    asm volatile(
        "mma.sync.aligned.m16n8k8.row.col.f32.tf32.tf32.f32 "
        "{%0,%1,%2,%3}, {%4,%5,%6,%7}, {%8,%9}, {%0,%1,%2,%3};"
        : "+f"(d[0]), "+f"(d[1]), "+f"(d[2]), "+f"(d[3])
        : "r"(a[0]), "r"(a[1]), "r"(a[2]), "r"(a[3]), "r"(b0), "r"(b1));
}
// exact gelu via A&S 7.1.26 erfc (|eps| <= 1.5e-7), branchless, coeffs pre-halved
__device__ __forceinline__ float gelu_fast(float h) {
    const float u  = h * 0.70710678118654752f;
    const float au = fabsf(u);
    const float t  = __fdividef(1.0f, fmaf(0.3275911f, au, 1.0f));
    float p = fmaf(t, 0.5307027145f, -0.7265760135f);
    p = fmaf(t, p, 0.7107068705f);
    p = fmaf(t, p, -0.142248368f);
    p = fmaf(t, p, 0.127414796f);
    p = p * t;
    const float q = p * __expf(-u * u);
    return h * ((h >= 0.f) ? (1.0f - q) : q);
}

__global__ void __launch_bounds__(THREADS, 1)
dig_mma3(const float* __restrict__ deg,
         const float* __restrict__ W1,
         const float* __restrict__ b1,
         const float* __restrict__ W2,
         const float* __restrict__ b2,
         const float* __restrict__ Wf,
         const float* __restrict__ bf,
         float* __restrict__ out)
{
    extern __shared__ float sm[];
    uint32_t* xw  = (uint32_t*)(sm + XS_OFF);
    float*    xs  = sm + XS_OFF;
    uint32_t* b1f = (uint32_t*)(sm + B1_OFF);
    uint32_t* b2f = (uint32_t*)(sm + B2_OFF);
    float*    b1s = sm + SM_B1S;
    float*    w2s = sm + SM_W2S;
    float*    bfs = sm + SM_BFS;
    float*    ssp = sm + SM_SSP;     // [2][6][128]
    float*    ss  = sm + SM_SS;      // [6][128]

    const int tid  = threadIdx.x;
    const int wid  = tid >> 5;
    const int lane = tid & 31;
    const int g    = lane >> 2;
    const int tig  = lane & 3;
    const int m0   = (wid & 7) << 4;
    const int half = wid >> 3;

    const int bb  = blockIdx.x >> 9;
    const int hw0 = (blockIdx.x & 511) << 7;

    // ---------------- stage X (float4 gmem -> tf32 STS.128) ----------------
    {
        const float* dptr = deg + (size_t)bb * 192 * 65536 + hw0;
        #pragma unroll 4
        for (int i = tid; i < 192 * 32; i += THREADS) {
            int c = i >> 5, p4 = (i & 31) << 2;
            float4 v = *(const float4*)(dptr + (size_t)c * 65536 + p4);
            uint4 w;
            w.x = f2tf32(v.x); w.y = f2tf32(v.y);
            w.z = f2tf32(v.z); w.w = f2tf32(v.w);
            *(uint4*)(xw + c * XS_W + p4) = w;
        }
    }
    // ---- stage W1 -> b1f fragment-major ----
    #pragma unroll 4
    for (int i = tid; i < 8192; i += THREADS) {
        int r = i >> 6, e = i & 63;
        int n = (r < 64) ? e : (64 + e);
        int k = r & 63;
        int addr = ((k >> 3) * 16 + (n >> 3)) * 64 + ((n & 7) * 4 + (k & 3)) * 2 + ((k >> 2) & 1);
        b1f[addr] = f2tf32(W1[i]);
    }
    // ---- stage Wf -> b2f fragment-major ----
    #pragma unroll 4
    for (int i = tid; i < 12288; i += THREADS) {
        int r = i >> 6, c = i & 63;
        int addr = ((r >> 3) * 8 + (c >> 3)) * 64 + ((c & 7) * 4 + (r & 3)) * 2 + ((r >> 2) & 1);
        b2f[addr] = f2tf32(Wf[i]);
    }
    if (tid < 64) { b1s[tid] = b1[tid]; w2s[tid] = W2[tid]; bfs[tid] = bf[tid]; }
    __syncthreads();

    // -------- GEMM1 (tf32 MMA) + in-register gating, e-half per warp --------
    float sp[6][2] = {{0.f,0.f},{0.f,0.f},{0.f,0.f},{0.f,0.f},{0.f,0.f},{0.f,0.f}};
    const uint32_t* xpt = xw + tig * XS_W + m0 + g;
    const uint32_t* b1p = b1f + lane * 2;
    #pragma unroll
    for (int qq = 0; qq < 2; qq++) {
        const int qt = half * 2 + qq;
        float accA[3][2][4], accC[3][2][4];
        #pragma unroll
        for (int t = 0; t < 3; t++)
            #pragma unroll
            for (int n = 0; n < 2; n++)
                #pragma unroll
                for (int r = 0; r < 4; r++) { accA[t][n][r] = 0.f; accC[t][n][r] = 0.f; }

        #pragma unroll
        for (int k = 0; k < 8; k++) {
            uint32_t af[3][4];
            #pragma unroll
            for (int t = 0; t < 3; t++) {
                const int c0 = t * 64 + k * 8;
                af[t][0] = xpt[c0 * XS_W];
                af[t][1] = xpt[c0 * XS_W + 8];
                af[t][2] = xpt[(c0 + 4) * XS_W];
                af[t][3] = xpt[(c0 + 4) * XS_W + 8];
            }
            #pragma unroll
            for (int nt = 0; nt < 2; nt++) {
                const int nb = qt * 2 + nt;
                uint2 av = *(const uint2*)(b1p + (k * 16 + nb) * 64);
                #pragma unroll
                for (int t = 0; t < 3; t++) mma8(accA[t][nt], af[t], av.x, av.y);
                uint2 cv = *(const uint2*)(b1p + (k * 16 + 8 + nb) * 64);
                #pragma unroll
                for (int t = 0; t < 3; t++) mma8(accC[t][nt], af[t], cv.x, cv.y);
            }
        }
        // gating partials
        #pragma unroll
        for (int nt = 0; nt < 2; nt++) {
            #pragma unroll
            for (int cc = 0; cc < 2; cc++) {
                const int e = qt * 16 + nt * 8 + 2 * tig + cc;
                const float bbv = b1s[e];
                const float wv  = w2s[e];
                #pragma unroll
                for (int r = 0; r < 2; r++) {
                    const int ri = 2 * r + cc;
                    sp[0][r] = fmaf(gelu_fast(accA[0][nt][ri] + accC[1][nt][ri] + bbv), wv, sp[0][r]);
                    sp[1][r] = fmaf(gelu_fast(accA[0][nt][ri] + accC[2][nt][ri] + bbv), wv, sp[1][r]);
                    sp[2][r] = fmaf(gelu_fast(accA[1][nt][ri] + accC[0][nt][ri] + bbv), wv, sp[2][r]);
                    sp[3][r] = fmaf(gelu_fast(accA[1][nt][ri] + accC[2][nt][ri] + bbv), wv, sp[3][r]);
                    sp[4][r] = fmaf(gelu_fast(accA[2][nt][ri] + accC[0][nt][ri] + bbv), wv, sp[4][r]);
                    sp[5][r] = fmaf(gelu_fast(accA[2][nt][ri] + accC[1][nt][ri] + bbv), wv, sp[5][r]);
                }
            }
        }
    }
    // 4-lane reduce, write per-half partials
    {
        #pragma unroll
        for (int q = 0; q < 6; q++) {
            #pragma unroll
            for (int r = 0; r < 2; r++) {
                float v = sp[q][r];
                v += __shfl_down_sync(0xffffffffu, v, 2, 4);
                v += __shfl_down_sync(0xffffffffu, v, 1, 4);
                if (tig == 0)
                    ssp[half * 768 + q * 128 + m0 + g + 8 * r] = v;
            }
        }
    }
    __syncthreads();
    {
        const float b2v = b2[0];
        #pragma unroll
        for (int i = tid; i < 768; i += THREADS)
            ss[i] = 1.0f / (1.0f + __expf(-(ssp[i] + ssp[768 + i] + b2v)));
    }
    __syncthreads();

    // -------- Y phase: xs <- M * x in place, 2 pixels per thread --------
    {
        const int pp = (tid & 63) << 1;
        const int d0 = (tid >> 6) << 3;     // 8 d per thread
        const float2 n01 = *(const float2*)(ss + 0 * 128 + pp);
        const float2 n02 = *(const float2*)(ss + 1 * 128 + pp);
        const float2 n10 = *(const float2*)(ss + 2 * 128 + pp);
        const float2 n12 = *(const float2*)(ss + 3 * 128 + pp);
        const float2 n20 = *(const float2*)(ss + 4 * 128 + pp);
        const float2 n21 = *(const float2*)(ss + 5 * 128 + pp);
        #pragma unroll
        for (int d = d0; d < d0 + 8; d++) {
            float2 x0 = *(const float2*)(xs + d * XS_W + pp);
            float2 x1 = *(const float2*)(xs + (64 + d) * XS_W + pp);
            float2 x2 = *(const float2*)(xs + (128 + d) * XS_W + pp);
            uint2 y0, y1, y2;
            y0.x = f2tf32(fmaf(n02.x, x2.x, fmaf(n01.x, x1.x, x0.x)));
            y0.y = f2tf32(fmaf(n02.y, x2.y, fmaf(n01.y, x1.y, x0.y)));
            y1.x = f2tf32(fmaf(n12.x, x2.x, fmaf(n10.x, x0.x, x1.x)));
            y1.y = f2tf32(fmaf(n12.y, x2.y, fmaf(n10.y, x0.y, x1.y)));
            y2.x = f2tf32(fmaf(n21.x, x1.x, fmaf(n20.x, x0.x, x2.x)));
            y2.y = f2tf32(fmaf(n21.y, x1.y, fmaf(n20.y, x0.y, x2.y)));
            *(uint2*)(xw + d * XS_W + pp)         = y0;
            *(uint2*)(xw + (64 + d) * XS_W + pp)  = y1;
            *(uint2*)(xw + (128 + d) * XS_W + pp) = y2;
        }
    }
    __syncthreads();

    // -------- GEMM2: D[128,64] = Y[128,192] @ Wf, k-half per warp --------
    float D[8][4];
    #pragma unroll
    for (int n = 0; n < 8; n++)
        #pragma unroll
        for (int r = 0; r < 4; r++) D[n][r] = 0.f;

    {
        const uint32_t* b2p = b2f + lane * 2;
        const int k0 = half * 12;
        #pragma unroll 4
        for (int k = k0; k < k0 + 12; k++) {
            const int c0 = k * 8;
            uint32_t af[4];
            af[0] = xpt[c0 * XS_W];
            af[1] = xpt[c0 * XS_W + 8];
            af[2] = xpt[(c0 + 4) * XS_W];
            af[3] = xpt[(c0 + 4) * XS_W + 8];
            #pragma unroll
            for (int n = 0; n < 8; n++) {
                uint2 bv = *(const uint2*)(b2p + (k * 8 + n) * 64);
                mma8(D[n], af, bv.x, bv.y);
            }
        }
    }
    __syncthreads();

    // -------- cross-half D reduction + epilogue --------
    float* stgB = (float*)b1f;       // [64][132] (spills into b2f region; both free now)
    if (half == 1) {
        #pragma unroll
        for (int n = 0; n < 8; n++) {
            #pragma unroll
            for (int cc = 0; cc < 2; cc++) {
                const int col = n * 8 + 2 * tig + cc;
                stgB[col * 132 + m0 + g]     = D[n][cc];
                stgB[col * 132 + m0 + g + 8] = D[n][2 + cc];
            }
        }
    }
    __syncthreads();
    float* stgA = sm + XS_OFF;       // reuse xs region: [64][136]
    if (half == 0) {
        #pragma unroll
        for (int n = 0; n < 8; n++) {
            #pragma unroll
            for (int cc = 0; cc < 2; cc++) {
                const int col = n * 8 + 2 * tig + cc;
                const float bfv = bfs[col];
                stgA[col * XS_W + m0 + g] =
                    D[n][cc] + stgB[col * 132 + m0 + g] + bfv;
                stgA[col * XS_W + m0 + g + 8] =
                    D[n][2 + cc] + stgB[col * 132 + m0 + g + 8] + bfv;
            }
        }
    }
    __syncthreads();
    {
        float* op = out + (size_t)bb * 64 * 65536 + hw0;
        #pragma unroll 4
        for (int i = tid; i < 64 * 32; i += THREADS) {
            int o = i >> 5, p4 = (i & 31) << 2;
            float4 v = *(const float4*)(stgA + o * XS_W + p4);
            *(float4*)(op + (size_t)o * 65536 + p4) = v;
        }
    }
}

extern "C" void kernel_launch(void* const* d_in, const int* in_sizes, int n_in,
                              void* d_out, int out_size)
{
    const float* deg = (const float*)d_in[0];
    const float* W1  = (const float*)d_in[1];
    const float* b1  = (const float*)d_in[2];
    const float* W2  = (const float*)d_in[3];
    const float* b2  = (const float*)d_in[4];
    const float* Wf  = (const float*)d_in[5];
    const float* bf  = (const float*)d_in[6];
    float* outp = (float*)d_out;

    cudaFuncSetAttribute(dig_mma3, cudaFuncAttributeMaxDynamicSharedMemorySize, SM_BYTES);
    dig_mma3<<<NBLOCKS, THREADS, SM_BYTES>>>(deg, W1, b1, W2, b2, Wf, bf, outp);
}

// round 6
// speedup vs baseline: 5.5210x; 1.1758x over previous
#include <cuda_runtime.h>
#include <cstdint>
#include <math.h>

#define THREADS  256
#define PPB      64
#define NBLOCKS  4096

// ---- smem layout (32-bit words) ----
// xs  : [192][72] tf32 bits of X (later Y bits); epilogue reuse: stgA[64][72]
// b1f : 8192 words fragment-major [kb(8)][nb(16)][lane(32)][2] (W1a^T;W1c^T)
//       reused as stgB[64][68] in epilogue
#define XS_W   72
#define XS_OFF 0
#define B1_OFF (192 * XS_W)                 // 13824
#define SM_B1S (B1_OFF + 8192)              // 22016
#define SM_W2S (SM_B1S + 64)
#define SM_BFS (SM_W2S + 64)
#define SM_SSP (SM_BFS + 64)                // 2*6*64 = 768
#define SM_SS  (SM_SSP + 768)               // 6*64 = 384
#define SM_FLOATS (SM_SS + 384)
#define SM_BYTES (SM_FLOATS * 4)            // 93440 B

// Wf fragment buffer in global scratch (L2-resident, written by prep kernel)
__device__ uint32_t g_wf_frag[12288];

__device__ __forceinline__ uint32_t f2tf32(float v) {
    uint32_t o;
    asm("cvt.rna.tf32.f32 %0, %1;" : "=r"(o) : "f"(v));
    return o;
}
__device__ __forceinline__ void mma8(float d[4], const uint32_t a[4],
                                     uint32_t b0, uint32_t b1) {
    asm volatile(
        "mma.sync.aligned.m16n8k8.row.col.f32.tf32.tf32.f32 "
        "{%0,%1,%2,%3}, {%4,%5,%6,%7}, {%8,%9}, {%0,%1,%2,%3};"
        : "+f"(d[0]), "+f"(d[1]), "+f"(d[2]), "+f"(d[3])
        : "r"(a[0]), "r"(a[1]), "r"(a[2]), "r"(a[3]), "r"(b0), "r"(b1));
}
// exact gelu via A&S 7.1.26 erfc (|eps| <= 1.5e-7), branchless
__device__ __forceinline__ float gelu_fast(float h) {
    const float u  = h * 0.70710678118654752f;
    const float au = fabsf(u);
    const float t  = __fdividef(1.0f, fmaf(0.3275911f, au, 1.0f));
    float p = fmaf(t, 0.5307027145f, -0.7265760135f);
    p = fmaf(t, p, 0.7107068705f);
    p = fmaf(t, p, -0.142248368f);
    p = fmaf(t, p, 0.127414796f);
    p = p * t;
    const float q = p * __expf(-u * u);
    return h * ((h >= 0.f) ? (1.0f - q) : q);
}

__global__ void __launch_bounds__(512)
prep_wf(const float* __restrict__ Wf) {
    int i = blockIdx.x * 512 + threadIdx.x;   // 0..12287
    int r = i >> 6, c = i & 63;
    int addr = ((r >> 3) * 8 + (c >> 3)) * 64 + ((c & 7) * 4 + (r & 3)) * 2 + ((r >> 2) & 1);
    g_wf_frag[addr] = f2tf32(Wf[i]);
}

__global__ void __launch_bounds__(THREADS, 2)
dig_mma4(const float* __restrict__ deg,
         const float* __restrict__ W1,
         const float* __restrict__ b1,
         const float* __restrict__ W2,
         const float* __restrict__ b2,
         const float* __restrict__ bf,
         float* __restrict__ out)
{
    extern __shared__ float sm[];
    uint32_t* xw  = (uint32_t*)(sm + XS_OFF);
    float*    xs  = sm + XS_OFF;
    uint32_t* b1f = (uint32_t*)(sm + B1_OFF);
    float*    b1s = sm + SM_B1S;
    float*    w2s = sm + SM_W2S;
    float*    bfs = sm + SM_BFS;
    float*    ssp = sm + SM_SSP;     // [2][6][64]
    float*    ss  = sm + SM_SS;      // [6][64]

    const int tid  = threadIdx.x;
    const int wid  = tid >> 5;
    const int lane = tid & 31;
    const int g    = lane >> 2;
    const int tig  = lane & 3;
    const int m0   = (wid & 3) << 4;   // 4 pixel tiles of 16
    const int half = wid >> 2;         // 0/1

    const int bb  = blockIdx.x >> 10;
    const int hw0 = (blockIdx.x & 1023) << 6;

    // ---------------- stage X (float4 gmem -> tf32 STS.128) ----------------
    {
        const float* dptr = deg + (size_t)bb * 192 * 65536 + hw0;
        #pragma unroll 4
        for (int i = tid; i < 192 * 16; i += THREADS) {
            int c = i >> 4, p4 = (i & 15) << 2;
            float4 v = *(const float4*)(dptr + (size_t)c * 65536 + p4);
            uint4 w;
            w.x = f2tf32(v.x); w.y = f2tf32(v.y);
            w.z = f2tf32(v.z); w.w = f2tf32(v.w);
            *(uint4*)(xw + c * XS_W + p4) = w;
        }
    }
    // ---- stage W1 -> b1f fragment-major ----
    #pragma unroll 4
    for (int i = tid; i < 8192; i += THREADS) {
        int r = i >> 6, e = i & 63;
        int n = (r < 64) ? e : (64 + e);
        int k = r & 63;
        int addr = ((k >> 3) * 16 + (n >> 3)) * 64 + ((n & 7) * 4 + (k & 3)) * 2 + ((k >> 2) & 1);
        b1f[addr] = f2tf32(W1[i]);
    }
    if (tid < 64) { b1s[tid] = b1[tid]; w2s[tid] = W2[tid]; bfs[tid] = bf[tid]; }
    __syncthreads();

    // -------- GEMM1 (tf32 MMA) + in-register gating, e-half per warp --------
    float sp[6][2] = {{0.f,0.f},{0.f,0.f},{0.f,0.f},{0.f,0.f},{0.f,0.f},{0.f,0.f}};
    const uint32_t* xpt = xw + tig * XS_W + m0 + g;
    const uint32_t* b1p = b1f + lane * 2;
    #pragma unroll
    for (int qq = 0; qq < 2; qq++) {
        const int qt = half * 2 + qq;
        float accA[3][2][4], accC[3][2][4];
        #pragma unroll
        for (int t = 0; t < 3; t++)
            #pragma unroll
            for (int n = 0; n < 2; n++)
                #pragma unroll
                for (int r = 0; r < 4; r++) { accA[t][n][r] = 0.f; accC[t][n][r] = 0.f; }

        #pragma unroll
        for (int k = 0; k < 8; k++) {
            uint32_t af[3][4];
            #pragma unroll
            for (int t = 0; t < 3; t++) {
                const int c0 = t * 64 + k * 8;
                af[t][0] = xpt[c0 * XS_W];
                af[t][1] = xpt[c0 * XS_W + 8];
                af[t][2] = xpt[(c0 + 4) * XS_W];
                af[t][3] = xpt[(c0 + 4) * XS_W + 8];
            }
            #pragma unroll
            for (int nt = 0; nt < 2; nt++) {
                const int nb = qt * 2 + nt;
                uint2 av = *(const uint2*)(b1p + (k * 16 + nb) * 64);
                #pragma unroll
                for (int t = 0; t < 3; t++) mma8(accA[t][nt], af[t], av.x, av.y);
                uint2 cv = *(const uint2*)(b1p + (k * 16 + 8 + nb) * 64);
                #pragma unroll
                for (int t = 0; t < 3; t++) mma8(accC[t][nt], af[t], cv.x, cv.y);
            }
        }
        // gating partials
        #pragma unroll
        for (int nt = 0; nt < 2; nt++) {
            #pragma unroll
            for (int cc = 0; cc < 2; cc++) {
                const int e = qt * 16 + nt * 8 + 2 * tig + cc;
                const float bbv = b1s[e];
                const float wv  = w2s[e];
                #pragma unroll
                for (int r = 0; r < 2; r++) {
                    const int ri = 2 * r + cc;
                    sp[0][r] = fmaf(gelu_fast(accA[0][nt][ri] + accC[1][nt][ri] + bbv), wv, sp[0][r]);
                    sp[1][r] = fmaf(gelu_fast(accA[0][nt][ri] + accC[2][nt][ri] + bbv), wv, sp[1][r]);
                    sp[2][r] = fmaf(gelu_fast(accA[1][nt][ri] + accC[0][nt][ri] + bbv), wv, sp[2][r]);
                    sp[3][r] = fmaf(gelu_fast(accA[1][nt][ri] + accC[2][nt][ri] + bbv), wv, sp[3][r]);
                    sp[4][r] = fmaf(gelu_fast(accA[2][nt][ri] + accC[0][nt][ri] + bbv), wv, sp[4][r]);
                    sp[5][r] = fmaf(gelu_fast(accA[2][nt][ri] + accC[1][nt][ri] + bbv), wv, sp[5][r]);
                }
            }
        }
    }
    // 4-lane reduce, write per-half partials
    {
        #pragma unroll
        for (int q = 0; q < 6; q++) {
            #pragma unroll
            for (int r = 0; r < 2; r++) {
                float v = sp[q][r];
                v += __shfl_down_sync(0xffffffffu, v, 2, 4);
                v += __shfl_down_sync(0xffffffffu, v, 1, 4);
                if (tig == 0)
                    ssp[half * 384 + q * 64 + m0 + g + 8 * r] = v;
            }
        }
    }
    __syncthreads();
    {
        const float b2v = b2[0];
        #pragma unroll
        for (int i = tid; i < 384; i += THREADS)
            ss[i] = 1.0f / (1.0f + __expf(-(ssp[i] + ssp[384 + i] + b2v)));
    }
    __syncthreads();

    // -------- Y phase: xs <- M * x in place, 2 pixels per thread --------
    {
        const int pp = (tid & 31) << 1;
        const int d0 = (tid >> 5) << 3;     // 8 d per thread
        const float2 n01 = *(const float2*)(ss + 0 * 64 + pp);
        const float2 n02 = *(const float2*)(ss + 1 * 64 + pp);
        const float2 n10 = *(const float2*)(ss + 2 * 64 + pp);
        const float2 n12 = *(const float2*)(ss + 3 * 64 + pp);
        const float2 n20 = *(const float2*)(ss + 4 * 64 + pp);
        const float2 n21 = *(const float2*)(ss + 5 * 64 + pp);
        #pragma unroll
        for (int d = d0; d < d0 + 8; d++) {
            float2 x0 = *(const float2*)(xs + d * XS_W + pp);
            float2 x1 = *(const float2*)(xs + (64 + d) * XS_W + pp);
            float2 x2 = *(const float2*)(xs + (128 + d) * XS_W + pp);
            uint2 y0, y1, y2;
            y0.x = f2tf32(fmaf(n02.x, x2.x, fmaf(n01.x, x1.x, x0.x)));
            y0.y = f2tf32(fmaf(n02.y, x2.y, fmaf(n01.y, x1.y, x0.y)));
            y1.x = f2tf32(fmaf(n12.x, x2.x, fmaf(n10.x, x0.x, x1.x)));
            y1.y = f2tf32(fmaf(n12.y, x2.y, fmaf(n10.y, x0.y, x1.y)));
            y2.x = f2tf32(fmaf(n21.x, x1.x, fmaf(n20.x, x0.x, x2.x)));
            y2.y = f2tf32(fmaf(n21.y, x1.y, fmaf(n20.y, x0.y, x2.y)));
            *(uint2*)(xw + d * XS_W + pp)         = y0;
            *(uint2*)(xw + (64 + d) * XS_W + pp)  = y1;
            *(uint2*)(xw + (128 + d) * XS_W + pp) = y2;
        }
    }
    __syncthreads();

    // -------- GEMM2: D[64,64] = Y[64,192] @ Wf, k-half per warp --------
    // B fragments streamed from L2-resident global scratch (g_wf_frag)
    float D[8][4];
    #pragma unroll
    for (int n = 0; n < 8; n++)
        #pragma unroll
        for (int r = 0; r < 4; r++) D[n][r] = 0.f;

    {
        const uint32_t* b2p = g_wf_frag + lane * 2;
        const int k0 = half * 12;
        #pragma unroll 4
        for (int k = k0; k < k0 + 12; k++) {
            const int c0 = k * 8;
            uint32_t af[4];
            af[0] = xpt[c0 * XS_W];
            af[1] = xpt[c0 * XS_W + 8];
            af[2] = xpt[(c0 + 4) * XS_W];
            af[3] = xpt[(c0 + 4) * XS_W + 8];
            #pragma unroll
            for (int n = 0; n < 8; n++) {
                uint2 bv = __ldg((const uint2*)(b2p + (k * 8 + n) * 64));
                mma8(D[n], af, bv.x, bv.y);
            }
        }
    }
    __syncthreads();

    // -------- cross-half D reduction + epilogue --------
    float* stgB = (float*)b1f;       // [64][68]
    if (half == 1) {
        #pragma unroll
        for (int n = 0; n < 8; n++) {
            #pragma unroll
            for (int cc = 0; cc < 2; cc++) {
                const int col = n * 8 + 2 * tig + cc;
                stgB[col * 68 + m0 + g]     = D[n][cc];
                stgB[col * 68 + m0 + g + 8] = D[n][2 + cc];
            }
        }
    }
    __syncthreads();
    float* stgA = sm + XS_OFF;       // reuse xs region: [64][72]
    if (half == 0) {
        #pragma unroll
        for (int n = 0; n < 8; n++) {
            #pragma unroll
            for (int cc = 0; cc < 2; cc++) {
                const int col = n * 8 + 2 * tig + cc;
                const float bfv = bfs[col];
                stgA[col * XS_W + m0 + g] =
                    D[n][cc] + stgB[col * 68 + m0 + g] + bfv;
                stgA[col * XS_W + m0 + g + 8] =
                    D[n][2 + cc] + stgB[col * 68 + m0 + g + 8] + bfv;
            }
        }
    }
    __syncthreads();
    {
        float* op = out + (size_t)bb * 64 * 65536 + hw0;
        #pragma unroll 4
        for (int i = tid; i < 64 * 16; i += THREADS) {
            int o = i >> 4, p4 = (i & 15) << 2;
            float4 v = *(const float4*)(stgA + o * XS_W + p4);
            *(float4*)(op + (size_t)o * 65536 + p4) = v;
        }
    }
}

extern "C" void kernel_launch(void* const* d_in, const int* in_sizes, int n_in,
                              void* d_out, int out_size)
{
    const float* deg = (const float*)d_in[0];
    const float* W1  = (const float*)d_in[1];
    const float* b1  = (const float*)d_in[2];
    const float* W2  = (const float*)d_in[3];
    const float* b2  = (const float*)d_in[4];
    const float* Wf  = (const float*)d_in[5];
    const float* bf  = (const float*)d_in[6];
    float* outp = (float*)d_out;

    prep_wf<<<24, 512>>>(Wf);
    cudaFuncSetAttribute(dig_mma4, cudaFuncAttributeMaxDynamicSharedMemorySize, SM_BYTES);
    dig_mma4<<<NBLOCKS, THREADS, SM_BYTES>>>(deg, W1, b1, W2, b2, bf, outp);
}

// round 7
// speedup vs baseline: 6.3958x; 1.1584x over previous
#include <cuda_runtime.h>
#include <cstdint>
#include <math.h>

#define THREADS  256
#define PPB      64
#define NBLOCKS  4096

// ---- smem layout (32-bit words) ----
// xs  : [192][72] tf32 bits of X (never overwritten)
// stg : [2][64][68] GEMM2 half-partials
#define XS_W    72
#define XS_OFF  0
#define STG_OFF (192 * XS_W)                // 13824
#define SM_B1S  (STG_OFF + 2 * 64 * 68)     // 22528
#define SM_W2S  (SM_B1S + 64)
#define SM_BFS  (SM_W2S + 64)
#define SM_SSP  (SM_BFS + 64)               // 2*6*64
#define SM_SS   (SM_SSP + 768)              // 6*64
#define SM_FLOATS (SM_SS + 384)
#define SM_BYTES (SM_FLOATS * 4)            // 95488 B

// weight fragment buffers in global scratch (L2-resident, written by prep kernel)
__device__ uint32_t g_w1_frag[8192];
__device__ uint32_t g_wf_frag[12288];

__device__ __forceinline__ uint32_t f2tf32(float v) {
    uint32_t o;
    asm("cvt.rna.tf32.f32 %0, %1;" : "=r"(o) : "f"(v));
    return o;
}
__device__ __forceinline__ void mma8(float d[4], const uint32_t a[4],
                                     uint32_t b0, uint32_t b1) {
    asm volatile(
        "mma.sync.aligned.m16n8k8.row.col.f32.tf32.tf32.f32 "
        "{%0,%1,%2,%3}, {%4,%5,%6,%7}, {%8,%9}, {%0,%1,%2,%3};"
        : "+f"(d[0]), "+f"(d[1]), "+f"(d[2]), "+f"(d[3])
        : "r"(a[0]), "r"(a[1]), "r"(a[2]), "r"(a[3]), "r"(b0), "r"(b1));
}
// exact gelu via A&S 7.1.26 erfc (|eps| <= 1.5e-7), branchless
__device__ __forceinline__ float gelu_fast(float h) {
    const float u  = h * 0.70710678118654752f;
    const float au = fabsf(u);
    const float t  = __fdividef(1.0f, fmaf(0.3275911f, au, 1.0f));
    float p = fmaf(t, 0.5307027145f, -0.7265760135f);
    p = fmaf(t, p, 0.7107068705f);
    p = fmaf(t, p, -0.142248368f);
    p = fmaf(t, p, 0.127414796f);
    p = p * t;
    const float q = p * __expf(-u * u);
    return h * ((h >= 0.f) ? (1.0f - q) : q);
}

__global__ void __launch_bounds__(512)
prep_w(const float* __restrict__ W1, const float* __restrict__ Wf) {
    int i = blockIdx.x * 512 + threadIdx.x;
    if (i < 8192) {
        int r = i >> 6, e = i & 63;
        int n = (r < 64) ? e : (64 + e);
        int k = r & 63;
        int addr = ((k >> 3) * 16 + (n >> 3)) * 64 + ((n & 7) * 4 + (k & 3)) * 2 + ((k >> 2) & 1);
        g_w1_frag[addr] = f2tf32(W1[i]);
    } else if (i < 8192 + 12288) {
        int j = i - 8192;
        int r = j >> 6, c = j & 63;
        int addr = ((r >> 3) * 8 + (c >> 3)) * 64 + ((c & 7) * 4 + (r & 3)) * 2 + ((r >> 2) & 1);
        g_wf_frag[addr] = f2tf32(Wf[j]);
    }
}

__global__ void __launch_bounds__(THREADS, 2)
dig_mma5(const float* __restrict__ deg,
         const float* __restrict__ b1,
         const float* __restrict__ W2,
         const float* __restrict__ b2,
         const float* __restrict__ bf,
         float* __restrict__ out)
{
    extern __shared__ float sm[];
    uint32_t* xw  = (uint32_t*)(sm + XS_OFF);
    float*    stg = sm + STG_OFF;    // [2][64][68]
    float*    b1s = sm + SM_B1S;
    float*    w2s = sm + SM_W2S;
    float*    bfs = sm + SM_BFS;
    float*    ssp = sm + SM_SSP;     // [2][6][64]
    float*    ss  = sm + SM_SS;      // [6][64]

    const int tid  = threadIdx.x;
    const int wid  = tid >> 5;
    const int lane = tid & 31;
    const int g    = lane >> 2;
    const int tig  = lane & 3;
    const int m0   = (wid & 3) << 4;
    const int half = wid >> 2;

    const int bb  = blockIdx.x >> 10;
    const int hw0 = (blockIdx.x & 1023) << 6;

    // ---------------- stage X (float4 gmem -> tf32 STS.128) ----------------
    {
        const float* dptr = deg + (size_t)bb * 192 * 65536 + hw0;
        #pragma unroll 4
        for (int i = tid; i < 192 * 16; i += THREADS) {
            int c = i >> 4, p4 = (i & 15) << 2;
            float4 v = *(const float4*)(dptr + (size_t)c * 65536 + p4);
            uint4 w;
            w.x = f2tf32(v.x); w.y = f2tf32(v.y);
            w.z = f2tf32(v.z); w.w = f2tf32(v.w);
            *(uint4*)(xw + c * XS_W + p4) = w;
        }
    }
    if (tid < 64) { b1s[tid] = b1[tid]; w2s[tid] = W2[tid]; bfs[tid] = bf[tid]; }
    __syncthreads();

    // -------- GEMM1 (tf32 MMA, B from L2) + in-register gating --------
    float sp[6][2] = {{0.f,0.f},{0.f,0.f},{0.f,0.f},{0.f,0.f},{0.f,0.f},{0.f,0.f}};
    const uint32_t* xpt = xw + tig * XS_W + m0 + g;
    const uint32_t* b1g = g_w1_frag + lane * 2;
    #pragma unroll
    for (int qq = 0; qq < 2; qq++) {
        const int qt = half * 2 + qq;
        float accA[3][2][4], accC[3][2][4];
        #pragma unroll
        for (int t = 0; t < 3; t++)
            #pragma unroll
            for (int n = 0; n < 2; n++)
                #pragma unroll
                for (int r = 0; r < 4; r++) { accA[t][n][r] = 0.f; accC[t][n][r] = 0.f; }

        #pragma unroll
        for (int k = 0; k < 8; k++) {
            uint32_t af[3][4];
            #pragma unroll
            for (int t = 0; t < 3; t++) {
                const int c0 = t * 64 + k * 8;
                af[t][0] = xpt[c0 * XS_W];
                af[t][1] = xpt[c0 * XS_W + 8];
                af[t][2] = xpt[(c0 + 4) * XS_W];
                af[t][3] = xpt[(c0 + 4) * XS_W + 8];
            }
            #pragma unroll
            for (int nt = 0; nt < 2; nt++) {
                const int nb = qt * 2 + nt;
                uint2 av = __ldg((const uint2*)(b1g + (k * 16 + nb) * 64));
                #pragma unroll
                for (int t = 0; t < 3; t++) mma8(accA[t][nt], af[t], av.x, av.y);
                uint2 cv = __ldg((const uint2*)(b1g + (k * 16 + 8 + nb) * 64));
                #pragma unroll
                for (int t = 0; t < 3; t++) mma8(accC[t][nt], af[t], cv.x, cv.y);
            }
        }
        // gating partials
        #pragma unroll
        for (int nt = 0; nt < 2; nt++) {
            #pragma unroll
            for (int cc = 0; cc < 2; cc++) {
                const int e = qt * 16 + nt * 8 + 2 * tig + cc;
                const float bbv = b1s[e];
                const float wv  = w2s[e];
                #pragma unroll
                for (int r = 0; r < 2; r++) {
                    const int ri = 2 * r + cc;
                    sp[0][r] = fmaf(gelu_fast(accA[0][nt][ri] + accC[1][nt][ri] + bbv), wv, sp[0][r]);
                    sp[1][r] = fmaf(gelu_fast(accA[0][nt][ri] + accC[2][nt][ri] + bbv), wv, sp[1][r]);
                    sp[2][r] = fmaf(gelu_fast(accA[1][nt][ri] + accC[0][nt][ri] + bbv), wv, sp[2][r]);
                    sp[3][r] = fmaf(gelu_fast(accA[1][nt][ri] + accC[2][nt][ri] + bbv), wv, sp[3][r]);
                    sp[4][r] = fmaf(gelu_fast(accA[2][nt][ri] + accC[0][nt][ri] + bbv), wv, sp[4][r]);
                    sp[5][r] = fmaf(gelu_fast(accA[2][nt][ri] + accC[1][nt][ri] + bbv), wv, sp[5][r]);
                }
            }
        }
    }
    // 4-lane reduce, write per-half partials
    {
        #pragma unroll
        for (int q = 0; q < 6; q++) {
            #pragma unroll
            for (int r = 0; r < 2; r++) {
                float v = sp[q][r];
                v += __shfl_down_sync(0xffffffffu, v, 2, 4);
                v += __shfl_down_sync(0xffffffffu, v, 1, 4);
                if (tig == 0)
                    ssp[half * 384 + q * 64 + m0 + g + 8 * r] = v;
            }
        }
    }
    __syncthreads();
    {
        const float b2v = b2[0];
        #pragma unroll
        for (int i = tid; i < 384; i += THREADS)
            ss[i] = 1.0f / (1.0f + __expf(-(ssp[i] + ssp[384 + i] + b2v)));
    }
    __syncthreads();

    // -------- GEMM2 with fused Y-mix: D[64,64] = (M*X)[64,192] @ Wf --------
    float D[8][4];
    #pragma unroll
    for (int n = 0; n < 8; n++)
        #pragma unroll
        for (int r = 0; r < 4; r++) D[n][r] = 0.f;

    {
        // gate scalars for this thread's two accumulator rows
        const int p0 = m0 + g, p1 = p0 + 8;
        float mm[2][6];
        #pragma unroll
        for (int q = 0; q < 6; q++) { mm[0][q] = ss[q * 64 + p0]; mm[1][q] = ss[q * 64 + p1]; }

        const uint32_t* b2g = g_wf_frag + lane * 2;
        const int dd0 = half * 4;
        #pragma unroll
        for (int dd = dd0; dd < dd0 + 4; dd++) {
            const int c0 = dd * 8;
            // load X fragments for all three t at this d-octave
            float xf[3][4];
            #pragma unroll
            for (int t = 0; t < 3; t++) {
                const int cb = t * 64 + c0;
                xf[t][0] = __uint_as_float(xpt[cb * XS_W]);
                xf[t][1] = __uint_as_float(xpt[cb * XS_W + 8]);
                xf[t][2] = __uint_as_float(xpt[(cb + 4) * XS_W]);
                xf[t][3] = __uint_as_float(xpt[(cb + 4) * XS_W + 8]);
            }
            // per t: build y fragment in-register, then 8 MMAs
            #pragma unroll
            for (int t = 0; t < 3; t++) {
                const int u1 = (t == 0) ? 1 : 0;
                const int u2 = (t == 2) ? 1 : 2;
                uint32_t yf[4];
                #pragma unroll
                for (int r = 0; r < 4; r++) {
                    const int row = r & 1;    // regs 0,2 -> p0 ; 1,3 -> p1
                    float y = fmaf(mm[row][2 * t + 1], xf[u2][r],
                              fmaf(mm[row][2 * t],     xf[u1][r], xf[t][r]));
                    yf[r] = f2tf32(y);
                }
                const int kk = t * 8 + dd;    // k-octave in Wf
                #pragma unroll
                for (int n = 0; n < 8; n++) {
                    uint2 bv = __ldg((const uint2*)(b2g + (kk * 8 + n) * 64));
                    mma8(D[n], yf, bv.x, bv.y);
                }
            }
        }
    }

    // -------- per-half partial staging (disjoint smem; no pre-sync needed) --------
    {
        float* sh = stg + half * 4352;   // [64][68]
        #pragma unroll
        for (int n = 0; n < 8; n++) {
            #pragma unroll
            for (int cc = 0; cc < 2; cc++) {
                const int col = n * 8 + 2 * tig + cc;
                sh[col * 68 + m0 + g]     = D[n][cc];
                sh[col * 68 + m0 + g + 8] = D[n][2 + cc];
            }
        }
    }
    __syncthreads();

    // -------- combined epilogue: stg0 + stg1 + bf -> gmem (float4) --------
    {
        float* op = out + (size_t)bb * 64 * 65536 + hw0;
        #pragma unroll 4
        for (int i = tid; i < 64 * 16; i += THREADS) {
            int o = i >> 4, p4 = (i & 15) << 2;
            float4 v0 = *(const float4*)(stg + o * 68 + p4);
            float4 v1 = *(const float4*)(stg + 4352 + o * 68 + p4);
            const float bfv = bfs[o];
            float4 v;
            v.x = v0.x + v1.x + bfv;
            v.y = v0.y + v1.y + bfv;
            v.z = v0.z + v1.z + bfv;
            v.w = v0.w + v1.w + bfv;
            *(float4*)(op + (size_t)o * 65536 + p4) = v;
        }
    }
}

extern "C" void kernel_launch(void* const* d_in, const int* in_sizes, int n_in,
                              void* d_out, int out_size)
{
    const float* deg = (const float*)d_in[0];
    const float* W1  = (const float*)d_in[1];
    const float* b1  = (const float*)d_in[2];
    const float* W2  = (const float*)d_in[3];
    const float* b2  = (const float*)d_in[4];
    const float* Wf  = (const float*)d_in[5];
    const float* bf  = (const float*)d_in[6];
    float* outp = (float*)d_out;

    prep_w<<<40, 512>>>(W1, Wf);
    cudaFuncSetAttribute(dig_mma5, cudaFuncAttributeMaxDynamicSharedMemorySize, SM_BYTES);
    dig_mma5<<<NBLOCKS, THREADS, SM_BYTES>>>(deg, b1, W2, b2, bf, outp);
}

// round 8
// speedup vs baseline: 6.8473x; 1.0706x over previous
#include <cuda_runtime.h>
#include <cstdint>
#include <math.h>

#define THREADS  256
#define PPB      64
#define NBLOCKS  4096

// ---- smem layout (32-bit words) ----
// xfr : fragment-major tf32 X: [koct(24)][mtile(4)][lane(32)][w(4)] = 12288 words
// stg : [2][64][68] GEMM2 half-partials
#define STG_OFF 12288
#define SM_B1S  (STG_OFF + 2 * 64 * 68)     // 20992
#define SM_W2S  (SM_B1S + 64)
#define SM_BFS  (SM_W2S + 64)
#define SM_SSP  (SM_BFS + 64)               // 2*6*64
#define SM_SS   (SM_SSP + 768)              // 6*64
#define SM_FLOATS (SM_SS + 384)
#define SM_BYTES (SM_FLOATS * 4)            // 89344 B

// weight fragment buffers in global scratch (L2-resident, written by prep kernel)
__device__ uint32_t g_w1_frag[8192];
__device__ uint32_t g_wf_frag[12288];

__device__ __forceinline__ uint32_t f2tf32(float v) {
    uint32_t o;
    asm("cvt.rna.tf32.f32 %0, %1;" : "=r"(o) : "f"(v));
    return o;
}
__device__ __forceinline__ void mma8(float d[4], const uint32_t a[4],
                                     uint32_t b0, uint32_t b1) {
    asm volatile(
        "mma.sync.aligned.m16n8k8.row.col.f32.tf32.tf32.f32 "
        "{%0,%1,%2,%3}, {%4,%5,%6,%7}, {%8,%9}, {%0,%1,%2,%3};"
        : "+f"(d[0]), "+f"(d[1]), "+f"(d[2]), "+f"(d[3])
        : "r"(a[0]), "r"(a[1]), "r"(a[2]), "r"(a[3]), "r"(b0), "r"(b1));
}
// gelu via Page/Bowling: Phi(h) ~= sigma(1.5976h + 0.07056h^3), |dPhi| <= ~1.4e-4
__device__ __forceinline__ float gelu_b(float h) {
    const float z = h * fmaf(h * h, 0.07056f, 1.5976f);
    return __fdividef(h, 1.0f + __expf(-z));
}

__global__ void __launch_bounds__(512)
prep_w(const float* __restrict__ W1, const float* __restrict__ Wf) {
    int i = blockIdx.x * 512 + threadIdx.x;
    if (i < 8192) {
        int r = i >> 6, e = i & 63;
        int n = (r < 64) ? e : (64 + e);
        int k = r & 63;
        int addr = ((k >> 3) * 16 + (n >> 3)) * 64 + ((n & 7) * 4 + (k & 3)) * 2 + ((k >> 2) & 1);
        g_w1_frag[addr] = f2tf32(W1[i]);
    } else if (i < 8192 + 12288) {
        int j = i - 8192;
        int r = j >> 6, c = j & 63;
        int addr = ((r >> 3) * 8 + (c >> 3)) * 64 + ((c & 7) * 4 + (r & 3)) * 2 + ((r >> 2) & 1);
        g_wf_frag[addr] = f2tf32(Wf[j]);
    }
}

__global__ void __launch_bounds__(THREADS, 2)
dig_mma6(const float* __restrict__ deg,
         const float* __restrict__ b1,
         const float* __restrict__ W2,
         const float* __restrict__ b2,
         const float* __restrict__ bf,
         float* __restrict__ out)
{
    extern __shared__ float sm[];
    uint32_t* xw  = (uint32_t*)sm;   // fragment-major tf32 X
    float*    stg = sm + STG_OFF;    // [2][64][68]
    float*    b1s = sm + SM_B1S;
    float*    w2s = sm + SM_W2S;
    float*    bfs = sm + SM_BFS;
    float*    ssp = sm + SM_SSP;     // [2][6][64]
    float*    ss  = sm + SM_SS;      // [6][64]

    const int tid  = threadIdx.x;
    const int wid  = tid >> 5;
    const int lane = tid & 31;
    const int g    = lane >> 2;
    const int tig  = lane & 3;
    const int m0   = (wid & 3) << 4;
    const int half = wid >> 2;

    const int bb  = blockIdx.x >> 10;
    const int hw0 = (blockIdx.x & 1023) << 6;

    // ------- stage X directly into fragment-major layout -------
    // word(koct, mtile, lane, w): w encodes {p or p+8} x {c or c+4}
    {
        const float* dptr = deg + (size_t)bb * 192 * 65536 + hw0;
        #pragma unroll
        for (int j = 0; j < 12; j++) {
            const int slot = j * THREADS + tid;         // 0..3071
            const int koct = slot >> 7;
            const int mt   = (slot >> 5) & 3;
            const int ls   = slot & 31;
            const int p0 = (mt << 4) + (ls >> 2);
            const int c0 = (koct << 3) + (ls & 3);
            const float* q = dptr + (size_t)c0 * 65536 + p0;
            uint4 w;
            w.x = f2tf32(q[0]);
            w.y = f2tf32(q[8]);
            w.z = f2tf32(q[(size_t)4 * 65536]);
            w.w = f2tf32(q[(size_t)4 * 65536 + 8]);
            *(uint4*)(xw + slot * 4) = w;
        }
    }
    if (tid < 64) { b1s[tid] = b1[tid]; w2s[tid] = W2[tid]; bfs[tid] = bf[tid]; }
    __syncthreads();

    // per-thread A-fragment base (LDS.128 slot); octave stride = 512 words
    const uint32_t* xfr = xw + ((wid & 3) * 32 + lane) * 4;

    // -------- GEMM1 (tf32 MMA, B from L2) + in-register gating --------
    float sp[6][2] = {{0.f,0.f},{0.f,0.f},{0.f,0.f},{0.f,0.f},{0.f,0.f},{0.f,0.f}};
    const uint32_t* b1g = g_w1_frag + lane * 2;
    #pragma unroll
    for (int qq = 0; qq < 2; qq++) {
        const int qt = half * 2 + qq;
        float accA[3][2][4], accC[3][2][4];
        #pragma unroll
        for (int t = 0; t < 3; t++)
            #pragma unroll
            for (int n = 0; n < 2; n++)
                #pragma unroll
                for (int r = 0; r < 4; r++) { accA[t][n][r] = 0.f; accC[t][n][r] = 0.f; }

        #pragma unroll
        for (int k = 0; k < 8; k++) {
            uint32_t af[3][4];
            #pragma unroll
            for (int t = 0; t < 3; t++) {
                uint4 v = *(const uint4*)(xfr + (t * 8 + k) * 512);
                af[t][0] = v.x; af[t][1] = v.y; af[t][2] = v.z; af[t][3] = v.w;
            }
            #pragma unroll
            for (int nt = 0; nt < 2; nt++) {
                const int nb = qt * 2 + nt;
                uint2 av = __ldg((const uint2*)(b1g + (k * 16 + nb) * 64));
                #pragma unroll
                for (int t = 0; t < 3; t++) mma8(accA[t][nt], af[t], av.x, av.y);
                uint2 cv = __ldg((const uint2*)(b1g + (k * 16 + 8 + nb) * 64));
                #pragma unroll
                for (int t = 0; t < 3; t++) mma8(accC[t][nt], af[t], cv.x, cv.y);
            }
        }
        // gating partials
        #pragma unroll
        for (int nt = 0; nt < 2; nt++) {
            #pragma unroll
            for (int cc = 0; cc < 2; cc++) {
                const int e = qt * 16 + nt * 8 + 2 * tig + cc;
                const float bbv = b1s[e];
                const float wv  = w2s[e];
                #pragma unroll
                for (int r = 0; r < 2; r++) {
                    const int ri = 2 * r + cc;
                    sp[0][r] = fmaf(gelu_b(accA[0][nt][ri] + accC[1][nt][ri] + bbv), wv, sp[0][r]);
                    sp[1][r] = fmaf(gelu_b(accA[0][nt][ri] + accC[2][nt][ri] + bbv), wv, sp[1][r]);
                    sp[2][r] = fmaf(gelu_b(accA[1][nt][ri] + accC[0][nt][ri] + bbv), wv, sp[2][r]);
                    sp[3][r] = fmaf(gelu_b(accA[1][nt][ri] + accC[2][nt][ri] + bbv), wv, sp[3][r]);
                    sp[4][r] = fmaf(gelu_b(accA[2][nt][ri] + accC[0][nt][ri] + bbv), wv, sp[4][r]);
                    sp[5][r] = fmaf(gelu_b(accA[2][nt][ri] + accC[1][nt][ri] + bbv), wv, sp[5][r]);
                }
            }
        }
    }
    // 4-lane reduce, write per-half partials
    {
        #pragma unroll
        for (int q = 0; q < 6; q++) {
            #pragma unroll
            for (int r = 0; r < 2; r++) {
                float v = sp[q][r];
                v += __shfl_down_sync(0xffffffffu, v, 2, 4);
                v += __shfl_down_sync(0xffffffffu, v, 1, 4);
                if (tig == 0)
                    ssp[half * 384 + q * 64 + m0 + g + 8 * r] = v;
            }
        }
    }
    __syncthreads();
    {
        const float b2v = b2[0];
        #pragma unroll
        for (int i = tid; i < 384; i += THREADS)
            ss[i] = 1.0f / (1.0f + __expf(-(ssp[i] + ssp[384 + i] + b2v)));
    }
    __syncthreads();

    // -------- GEMM2 with fused Y-mix: D[64,64] = (M*X)[64,192] @ Wf --------
    float D[8][4];
    #pragma unroll
    for (int n = 0; n < 8; n++)
        #pragma unroll
        for (int r = 0; r < 4; r++) D[n][r] = 0.f;

    {
        const int p0 = m0 + g, p1 = p0 + 8;
        float mm[2][6];
        #pragma unroll
        for (int q = 0; q < 6; q++) { mm[0][q] = ss[q * 64 + p0]; mm[1][q] = ss[q * 64 + p1]; }

        const uint32_t* b2g = g_wf_frag + lane * 2;
        const int dd0 = half * 4;
        #pragma unroll
        for (int dd = dd0; dd < dd0 + 4; dd++) {
            float xf[3][4];
            #pragma unroll
            for (int t = 0; t < 3; t++) {
                uint4 v = *(const uint4*)(xfr + (t * 8 + dd) * 512);
                xf[t][0] = __uint_as_float(v.x);
                xf[t][1] = __uint_as_float(v.y);
                xf[t][2] = __uint_as_float(v.z);
                xf[t][3] = __uint_as_float(v.w);
            }
            #pragma unroll
            for (int t = 0; t < 3; t++) {
                const int u1 = (t == 0) ? 1 : 0;
                const int u2 = (t == 2) ? 1 : 2;
                uint32_t yf[4];
                #pragma unroll
                for (int r = 0; r < 4; r++) {
                    const int row = r & 1;   // w parity = pixel-row bit
                    float y = fmaf(mm[row][2 * t + 1], xf[u2][r],
                              fmaf(mm[row][2 * t],     xf[u1][r], xf[t][r]));
                    yf[r] = f2tf32(y);
                }
                const int kk = t * 8 + dd;
                #pragma unroll
                for (int n = 0; n < 8; n++) {
                    uint2 bv = __ldg((const uint2*)(b2g + (kk * 8 + n) * 64));
                    mma8(D[n], yf, bv.x, bv.y);
                }
            }
        }
    }

    // -------- per-half partial staging --------
    {
        float* sh = stg + half * 4352;   // [64][68]
        #pragma unroll
        for (int n = 0; n < 8; n++) {
            #pragma unroll
            for (int cc = 0; cc < 2; cc++) {
                const int col = n * 8 + 2 * tig + cc;
                sh[col * 68 + m0 + g]     = D[n][cc];
                sh[col * 68 + m0 + g + 8] = D[n][2 + cc];
            }
        }
    }
    __syncthreads();

    // -------- combined epilogue: stg0 + stg1 + bf -> gmem (float4) --------
    {
        float* op = out + (size_t)bb * 64 * 65536 + hw0;
        #pragma unroll 4
        for (int i = tid; i < 64 * 16; i += THREADS) {
            int o = i >> 4, p4 = (i & 15) << 2;
            float4 v0 = *(const float4*)(stg + o * 68 + p4);
            float4 v1 = *(const float4*)(stg + 4352 + o * 68 + p4);
            const float bfv = bfs[o];
            float4 v;
            v.x = v0.x + v1.x + bfv;
            v.y = v0.y + v1.y + bfv;
            v.z = v0.z + v1.z + bfv;
            v.w = v0.w + v1.w + bfv;
            *(float4*)(op + (size_t)o * 65536 + p4) = v;
        }
    }
}

extern "C" void kernel_launch(void* const* d_in, const int* in_sizes, int n_in,
                              void* d_out, int out_size)
{
    const float* deg = (const float*)d_in[0];
    const float* W1  = (const float*)d_in[1];
    const float* b1  = (const float*)d_in[2];
    const float* W2  = (const float*)d_in[3];
    const float* b2  = (const float*)d_in[4];
    const float* Wf  = (const float*)d_in[5];
    const float* bf  = (const float*)d_in[6];
    float* outp = (float*)d_out;

    prep_w<<<40, 512>>>(W1, Wf);
    cudaFuncSetAttribute(dig_mma6, cudaFuncAttributeMaxDynamicSharedMemorySize, SM_BYTES);
    dig_mma6<<<NBLOCKS, THREADS, SM_BYTES>>>(deg, b1, W2, b2, bf, outp);
}

// round 9
// speedup vs baseline: 6.8701x; 1.0033x over previous
#include <cuda_runtime.h>
#include <cstdint>
#include <math.h>

#define THREADS  256
#define PPB      64
#define NBLOCKS  4096

// ---- smem layout (32-bit words) ----
// xfr : fragment-major tf32 X: [koct(24)][mtile(4)][lane(32)][w(4)] = 12288 words
//       (reused after GEMM2 as stg[2][64][68] = 8704 words)
// w1s : 8192 words, W1 fragments copied from global prep buffer
#define W1S_OFF 12288
#define SM_B1S  (W1S_OFF + 8192)            // 20480
#define SM_W2S  (SM_B1S + 64)
#define SM_BFS  (SM_W2S + 64)
#define SM_SSP  (SM_BFS + 64)               // 2*6*64
#define SM_SS   (SM_SSP + 768)              // 6*64
#define SM_FLOATS (SM_SS + 384)
#define SM_BYTES (SM_FLOATS * 4)            // 87296 B

// weight fragment buffers in global scratch (written by prep kernel)
__device__ __align__(16) uint32_t g_w1_frag[8192];
__device__ __align__(16) uint32_t g_wf_frag[12288];

__device__ __forceinline__ uint32_t f2tf32(float v) {
    uint32_t o;
    asm("cvt.rna.tf32.f32 %0, %1;" : "=r"(o) : "f"(v));
    return o;
}
__device__ __forceinline__ void mma8(float d[4], const uint32_t a[4],
                                     uint32_t b0, uint32_t b1) {
    asm volatile(
        "mma.sync.aligned.m16n8k8.row.col.f32.tf32.tf32.f32 "
        "{%0,%1,%2,%3}, {%4,%5,%6,%7}, {%8,%9}, {%0,%1,%2,%3};"
        : "+f"(d[0]), "+f"(d[1]), "+f"(d[2]), "+f"(d[3])
        : "r"(a[0]), "r"(a[1]), "r"(a[2]), "r"(a[3]), "r"(b0), "r"(b1));
}
// gelu via Phi(h) ~= sigma(1.5976h + 0.07056h^3), |dPhi| <= ~1.4e-4
__device__ __forceinline__ float gelu_b(float h) {
    const float z = h * fmaf(h * h, 0.07056f, 1.5976f);
    return __fdividef(h, 1.0f + __expf(-z));
}

__global__ void __launch_bounds__(512)
prep_w(const float* __restrict__ W1, const float* __restrict__ Wf) {
    int i = blockIdx.x * 512 + threadIdx.x;
    if (i < 8192) {
        int r = i >> 6, e = i & 63;
        int n = (r < 64) ? e : (64 + e);
        int k = r & 63;
        int addr = ((k >> 3) * 16 + (n >> 3)) * 64 + ((n & 7) * 4 + (k & 3)) * 2 + ((k >> 2) & 1);
        g_w1_frag[addr] = f2tf32(W1[i]);
    } else if (i < 8192 + 12288) {
        int j = i - 8192;
        int r = j >> 6, c = j & 63;
        int addr = ((r >> 3) * 8 + (c >> 3)) * 64 + ((c & 7) * 4 + (r & 3)) * 2 + ((r >> 2) & 1);
        g_wf_frag[addr] = f2tf32(Wf[j]);
    }
}

__global__ void __launch_bounds__(THREADS, 2)
dig_mma7(const float* __restrict__ deg,
         const float* __restrict__ b1,
         const float* __restrict__ W2,
         const float* __restrict__ b2,
         const float* __restrict__ bf,
         float* __restrict__ out)
{
    extern __shared__ float sm[];
    uint32_t* xw  = (uint32_t*)sm;            // fragment-major tf32 X
    float*    stg = sm;                       // overlaid after GEMM2: [2][64][68]
    uint32_t* w1s = (uint32_t*)sm + W1S_OFF;
    float*    b1s = sm + SM_B1S;
    float*    w2s = sm + SM_W2S;
    float*    bfs = sm + SM_BFS;
    float*    ssp = sm + SM_SSP;     // [2][6][64]
    float*    ss  = sm + SM_SS;      // [6][64]

    const int tid  = threadIdx.x;
    const int wid  = tid >> 5;
    const int lane = tid & 31;
    const int g    = lane >> 2;
    const int tig  = lane & 3;
    const int m0   = (wid & 3) << 4;   // GEMM1 m-tile
    const int half = wid >> 2;         // GEMM1 e-half

    const int bb  = blockIdx.x >> 10;
    const int hw0 = (blockIdx.x & 1023) << 6;

    // ------- stage X into fragment-major layout -------
    {
        const float* dptr = deg + (size_t)bb * 192 * 65536 + hw0;
        #pragma unroll
        for (int j = 0; j < 12; j++) {
            const int slot = j * THREADS + tid;
            const int koct = slot >> 7;
            const int mt   = (slot >> 5) & 3;
            const int ls   = slot & 31;
            const int p0 = (mt << 4) + (ls >> 2);
            const int c0 = (koct << 3) + (ls & 3);
            const float* q = dptr + (size_t)c0 * 65536 + p0;
            uint4 w;
            w.x = f2tf32(q[0]);
            w.y = f2tf32(q[8]);
            w.z = f2tf32(q[(size_t)4 * 65536]);
            w.w = f2tf32(q[(size_t)4 * 65536 + 8]);
            *(uint4*)(xw + slot * 4) = w;
        }
    }
    // ------- copy W1 fragments into smem (coalesced uint4) -------
    #pragma unroll
    for (int i = tid; i < 2048; i += THREADS)
        ((uint4*)w1s)[i] = ((const uint4*)g_w1_frag)[i];
    if (tid < 64) { b1s[tid] = b1[tid]; w2s[tid] = W2[tid]; bfs[tid] = bf[tid]; }
    __syncthreads();

    const uint32_t* xfr = xw + ((wid & 3) * 32 + lane) * 4;

    // -------- GEMM1 (tf32 MMA, B from smem) + in-register gating --------
    float sp[6][2] = {{0.f,0.f},{0.f,0.f},{0.f,0.f},{0.f,0.f},{0.f,0.f},{0.f,0.f}};
    const uint32_t* b1p = w1s + lane * 2;
    #pragma unroll
    for (int qq = 0; qq < 2; qq++) {
        const int qt = half * 2 + qq;
        float accA[3][2][4], accC[3][2][4];
        #pragma unroll
        for (int t = 0; t < 3; t++)
            #pragma unroll
            for (int n = 0; n < 2; n++)
                #pragma unroll
                for (int r = 0; r < 4; r++) { accA[t][n][r] = 0.f; accC[t][n][r] = 0.f; }

        #pragma unroll
        for (int k = 0; k < 8; k++) {
            uint32_t af[3][4];
            #pragma unroll
            for (int t = 0; t < 3; t++) {
                uint4 v = *(const uint4*)(xfr + (t * 8 + k) * 512);
                af[t][0] = v.x; af[t][1] = v.y; af[t][2] = v.z; af[t][3] = v.w;
            }
            #pragma unroll
            for (int nt = 0; nt < 2; nt++) {
                const int nb = qt * 2 + nt;
                uint2 av = *(const uint2*)(b1p + (k * 16 + nb) * 64);
                #pragma unroll
                for (int t = 0; t < 3; t++) mma8(accA[t][nt], af[t], av.x, av.y);
                uint2 cv = *(const uint2*)(b1p + (k * 16 + 8 + nb) * 64);
                #pragma unroll
                for (int t = 0; t < 3; t++) mma8(accC[t][nt], af[t], cv.x, cv.y);
            }
        }
        // gating partials
        #pragma unroll
        for (int nt = 0; nt < 2; nt++) {
            #pragma unroll
            for (int cc = 0; cc < 2; cc++) {
                const int e = qt * 16 + nt * 8 + 2 * tig + cc;
                const float bbv = b1s[e];
                const float wv  = w2s[e];
                #pragma unroll
                for (int r = 0; r < 2; r++) {
                    const int ri = 2 * r + cc;
                    sp[0][r] = fmaf(gelu_b(accA[0][nt][ri] + accC[1][nt][ri] + bbv), wv, sp[0][r]);
                    sp[1][r] = fmaf(gelu_b(accA[0][nt][ri] + accC[2][nt][ri] + bbv), wv, sp[1][r]);
                    sp[2][r] = fmaf(gelu_b(accA[1][nt][ri] + accC[0][nt][ri] + bbv), wv, sp[2][r]);
                    sp[3][r] = fmaf(gelu_b(accA[1][nt][ri] + accC[2][nt][ri] + bbv), wv, sp[3][r]);
                    sp[4][r] = fmaf(gelu_b(accA[2][nt][ri] + accC[0][nt][ri] + bbv), wv, sp[4][r]);
                    sp[5][r] = fmaf(gelu_b(accA[2][nt][ri] + accC[1][nt][ri] + bbv), wv, sp[5][r]);
                }
            }
        }
    }
    // 4-lane reduce, write per-half partials
    {
        #pragma unroll
        for (int q = 0; q < 6; q++) {
            #pragma unroll
            for (int r = 0; r < 2; r++) {
                float v = sp[q][r];
                v += __shfl_down_sync(0xffffffffu, v, 2, 4);
                v += __shfl_down_sync(0xffffffffu, v, 1, 4);
                if (tig == 0)
                    ssp[half * 384 + q * 64 + m0 + g + 8 * r] = v;
            }
        }
    }
    __syncthreads();
    {
        const float b2v = b2[0];
        #pragma unroll
        for (int i = tid; i < 384; i += THREADS)
            ss[i] = 1.0f / (1.0f + __expf(-(ssp[i] + ssp[384 + i] + b2v)));
    }
    __syncthreads();

    // -------- GEMM2 with fused Y-mix + m-pairing --------
    // warp roles: mp = m-pair, kh = k-half (d-octaves), nh = n-half
    const int mp = wid & 1;
    const int kh = (wid >> 1) & 1;
    const int nh = wid >> 2;

    float D[2][4][4];
    #pragma unroll
    for (int mt = 0; mt < 2; mt++)
        #pragma unroll
        for (int n = 0; n < 4; n++)
            #pragma unroll
            for (int r = 0; r < 4; r++) D[mt][n][r] = 0.f;

    {
        float mm[2][2][6];   // [mt][row][pair]
        #pragma unroll
        for (int mt = 0; mt < 2; mt++) {
            const int p0 = (2 * mp + mt) * 16 + g;
            #pragma unroll
            for (int q = 0; q < 6; q++) {
                mm[mt][0][q] = ss[q * 64 + p0];
                mm[mt][1][q] = ss[q * 64 + p0 + 8];
            }
        }
        const uint32_t* b2g = g_wf_frag + lane * 2;
        const int dd0 = kh * 4;
        #pragma unroll
        for (int dd = dd0; dd < dd0 + 4; dd++) {
            uint32_t yfa[2][3][4];
            #pragma unroll
            for (int mt = 0; mt < 2; mt++) {
                const uint32_t* xm = xw + (((2 * mp + mt) * 32) + lane) * 4;
                float xf[3][4];
                #pragma unroll
                for (int t = 0; t < 3; t++) {
                    uint4 v = *(const uint4*)(xm + (t * 8 + dd) * 512);
                    xf[t][0] = __uint_as_float(v.x);
                    xf[t][1] = __uint_as_float(v.y);
                    xf[t][2] = __uint_as_float(v.z);
                    xf[t][3] = __uint_as_float(v.w);
                }
                #pragma unroll
                for (int t = 0; t < 3; t++) {
                    const int u1 = (t == 0) ? 1 : 0;
                    const int u2 = (t == 2) ? 1 : 2;
                    #pragma unroll
                    for (int r = 0; r < 4; r++) {
                        const int row = r & 1;   // regs 0,2 -> row g ; 1,3 -> row g+8
                        float y = fmaf(mm[mt][row][2 * t + 1], xf[u2][r],
                                  fmaf(mm[mt][row][2 * t],     xf[u1][r], xf[t][r]));
                        yfa[mt][t][r] = f2tf32(y);
                    }
                }
            }
            #pragma unroll
            for (int t = 0; t < 3; t++) {
                const int kk = t * 8 + dd;
                #pragma unroll
                for (int n = 0; n < 4; n++) {
                    uint2 bv = __ldg((const uint2*)(b2g + (kk * 8 + 4 * nh + n) * 64));
                    mma8(D[0][n], yfa[0][t], bv.x, bv.y);
                    mma8(D[1][n], yfa[1][t], bv.x, bv.y);
                }
            }
        }
    }
    __syncthreads();   // all xfr reads done; safe to overlay stg

    // -------- per-(kh) partial staging into overlaid stg --------
    {
        float* sh = stg + kh * 4352;   // [64][68]
        #pragma unroll
        for (int mt = 0; mt < 2; mt++) {
            const int row0 = (2 * mp + mt) * 16 + g;
            #pragma unroll
            for (int n = 0; n < 4; n++) {
                #pragma unroll
                for (int cc = 0; cc < 2; cc++) {
                    const int col = (4 * nh + n) * 8 + 2 * tig + cc;
                    sh[col * 68 + row0]     = D[mt][n][cc];
                    sh[col * 68 + row0 + 8] = D[mt][n][2 + cc];
                }
            }
        }
    }
    __syncthreads();

    // -------- combined epilogue: stg0 + stg1 + bf -> gmem (float4) --------
    {
        float* op = out + (size_t)bb * 64 * 65536 + hw0;
        #pragma unroll 4
        for (int i = tid; i < 64 * 16; i += THREADS) {
            int o = i >> 4, p4 = (i & 15) << 2;
            float4 v0 = *(const float4*)(stg + o * 68 + p4);
            float4 v1 = *(const float4*)(stg + 4352 + o * 68 + p4);
            const float bfv = bfs[o];
            float4 v;
            v.x = v0.x + v1.x + bfv;
            v.y = v0.y + v1.y + bfv;
            v.z = v0.z + v1.z + bfv;
            v.w = v0.w + v1.w + bfv;
            *(float4*)(op + (size_t)o * 65536 + p4) = v;
        }
    }
}

extern "C" void kernel_launch(void* const* d_in, const int* in_sizes, int n_in,
                              void* d_out, int out_size)
{
    const float* deg = (const float*)d_in[0];
    const float* W1  = (const float*)d_in[1];
    const float* b1  = (const float*)d_in[2];
    const float* W2  = (const float*)d_in[3];
    const float* b2  = (const float*)d_in[4];
    const float* Wf  = (const float*)d_in[5];
    const float* bf  = (const float*)d_in[6];
    float* outp = (float*)d_out;

    prep_w<<<40, 512>>>(W1, Wf);
    cudaFuncSetAttribute(dig_mma7, cudaFuncAttributeMaxDynamicSharedMemorySize, SM_BYTES);
    dig_mma7<<<NBLOCKS, THREADS, SM_BYTES>>>(deg, b1, W2, b2, bf, outp);
}